// round 10
// baseline (speedup 1.0000x reference)
#include <cuda_runtime.h>
#include <cstdint>
#include <math.h>

// ---------------- problem constants ----------------
#define T_TOK 1024
#define H_DIM 2048
#define I_DIM 1408
#define N_EXP 8

// ---------------- tiling ----------------
#define BM 128
#define BN 128
#define BK 64
#define NSTAGE 3
#define MAXSLOT  3072
#define MAXTILES 24
#define NTHREADS 512

#define SM_STRIDE 68      // floats per smem row (272 B; scalar frag banks 4g+tg distinct)
#define A_WORDS (BM * SM_STRIDE)                 // 8704 floats = 34 KB
#define STAGE_WORDS (2 * A_WORDS)                // A+B = 68 KB
#define SMEM_DYN_BYTES (NSTAGE * STAGE_WORDS * 4)   // 204 KB

// ---------------- scratch ----------------
__device__ int   g_token_of_slot[MAXSLOT];
__device__ float g_slot_weight[MAXSLOT];
__device__ int   g_tile_expert[MAXTILES];
__device__ int   g_num_tiles;
__device__ float g_act[(size_t)MAXSLOT * I_DIM];   // ~17.3 MB (stored tf32-pre-rounded)
__device__ float g_x32[(size_t)T_TOK * H_DIM];     // 8 MB   (x, tf32-pre-rounded)

// ---------------- PTX helpers (baseline sm_80+; nothing 'a'-gated) ----------------
__device__ __forceinline__ uint32_t smem_u32(const void* p) {
    uint32_t a;
    asm("{ .reg .u64 t; cvta.to.shared.u64 t, %1; cvt.u32.u64 %0, t; }" : "=r"(a) : "l"(p));
    return a;
}
#define CP_ASYNC16(dst_u32, src_ptr) \
    asm volatile("cp.async.cg.shared.global [%0], [%1], 16;" :: "r"(dst_u32), "l"(src_ptr))
#define CP_COMMIT()  asm volatile("cp.async.commit_group;" ::: "memory")
#define CP_WAIT(N)   asm volatile("cp.async.wait_group %0;" :: "n"(N) : "memory")

__device__ __forceinline__ uint32_t f2tf32(float f) {
    uint32_t r;
    asm("cvt.rna.tf32.f32 %0, %1;" : "=r"(r) : "f"(f));
    return r;
}
__device__ __forceinline__ void mma_tf32(float* c, const uint32_t* a, const uint32_t* b) {
    asm volatile(
        "mma.sync.aligned.m16n8k8.row.col.f32.tf32.tf32.f32 "
        "{%0,%1,%2,%3}, {%4,%5,%6,%7}, {%8,%9}, {%0,%1,%2,%3};"
        : "+f"(c[0]), "+f"(c[1]), "+f"(c[2]), "+f"(c[3])
        : "r"(a[0]), "r"(a[1]), "r"(a[2]), "r"(a[3]), "r"(b[0]), "r"(b[1]));
}

// ============================================================
// Pre-round x to tf32 (rna) so GEMM1 A-fragments need no in-loop cvt.
// ============================================================
__global__ void convert_x(const float* __restrict__ x) {
    const int i = (blockIdx.x * 256 + threadIdx.x) * 4;
    float4 v = *(const float4*)(x + i);
    float4 o;
    o.x = __uint_as_float(f2tf32(v.x));
    o.y = __uint_as_float(f2tf32(v.y));
    o.z = __uint_as_float(f2tf32(v.z));
    o.w = __uint_as_float(f2tf32(v.w));
    *(float4*)(g_x32 + i) = o;
}

// ============================================================
// Routing: softmax -> top2 -> renormalize; padded per-expert slot lists (x128).
// ============================================================
__global__ void routing_kernel(const float* __restrict__ logits) {
    __shared__ int s_cnt[N_EXP];
    __shared__ int s_cur[N_EXP];
    __shared__ int s_off[N_EXP + 1];

    const int t = threadIdx.x;
    if (t < N_EXP) { s_cnt[t] = 0; s_cur[t] = 0; }
    for (int s = t; s < MAXSLOT; s += blockDim.x) g_token_of_slot[s] = -1;
    __syncthreads();

    int e1 = 0, e2 = 0;
    float w1 = 0.f, w2 = 0.f;
    if (t < T_TOK) {
        float l[N_EXP];
#pragma unroll
        for (int e = 0; e < N_EXP; e++) l[e] = logits[t * N_EXP + e];
        float b1 = -1e30f;
#pragma unroll
        for (int e = 0; e < N_EXP; e++) if (l[e] > b1) { b1 = l[e]; e1 = e; }
        float b2 = -1e30f;
        e2 = (e1 == 0) ? 1 : 0;
#pragma unroll
        for (int e = 0; e < N_EXP; e++) if (e != e1 && l[e] > b2) { b2 = l[e]; e2 = e; }
        float p2 = expf(b2 - b1);
        w1 = 1.f / (1.f + p2);
        w2 = p2 / (1.f + p2);
        atomicAdd(&s_cnt[e1], 1);
        atomicAdd(&s_cnt[e2], 1);
    }
    __syncthreads();

    if (t == 0) {
        int off = 0;
        for (int e = 0; e < N_EXP; e++) {
            s_off[e] = off;
            int tiles = (s_cnt[e] + BM - 1) / BM;
            for (int i = 0; i < tiles; i++) g_tile_expert[off / BM + i] = e;
            off += tiles * BM;
        }
        s_off[N_EXP] = off;
        g_num_tiles = off / BM;
    }
    __syncthreads();

    if (t < T_TOK) {
        int p = atomicAdd(&s_cur[e1], 1);
        int s = s_off[e1] + p;
        g_token_of_slot[s] = t;
        g_slot_weight[s]   = w1;
        p = atomicAdd(&s_cur[e2], 1);
        s = s_off[e2] + p;
        g_token_of_slot[s] = t;
        g_slot_weight[s]   = w2;
    }
}

// ============================================================
// Fragment context + per-chunk MMA (tf32 m16n8k8).
// 16 warps: wm = wid&3 (32 rows), wn = wid>>2 (32 cols); warp tile 32x32.
// A fragments are RAW bits (inputs pre-rounded); B fragments cvt in-loop.
// Chunk = 8 k8-steps (BK=64).
// ============================================================
struct FragCtx { int wm, wn, g, tg; };

__device__ __forceinline__ void mma_chunk(const float* __restrict__ A,
                                          const float* __restrict__ B,
                                          const FragCtx& f,
                                          float acc[2][4][4]) {
    const uint32_t* Au = (const uint32_t*)A;
#pragma unroll
    for (int ks = 0; ks < 8; ks++) {
        uint32_t af[2][4];
#pragma unroll
        for (int mf = 0; mf < 2; mf++) {
            const int row = f.wm * 32 + mf * 16 + f.g;
            const int base = row * SM_STRIDE + ks * 8 + f.tg;
            af[mf][0] = Au[base];
            af[mf][1] = Au[base + 8 * SM_STRIDE];
            af[mf][2] = Au[base + 4];
            af[mf][3] = Au[base + 8 * SM_STRIDE + 4];
        }
        uint32_t bf[4][2];
#pragma unroll
        for (int nf = 0; nf < 4; nf++) {
            const int n = f.wn * 32 + nf * 8 + f.g;
            const int base = n * SM_STRIDE + ks * 8 + f.tg;
            bf[nf][0] = f2tf32(B[base]);
            bf[nf][1] = f2tf32(B[base + 4]);
        }
#pragma unroll
        for (int mf = 0; mf < 2; mf++)
#pragma unroll
            for (int nf = 0; nf < 4; nf++)
                mma_tf32(acc[mf][nf], af[mf], bf[nf]);
    }
}

// loaders: 512 threads; each thread 4 A segs + 4 B segs of 16B (BK=64 -> 256B/row)
__device__ __forceinline__ void issue_chunk(uint32_t aDst, uint32_t bDst,
                                            const float* aSrc, const float* bSrc,
                                            int kOff, int sb) {
#pragma unroll
    for (int i = 0; i < 4; i++) {
        CP_ASYNC16(aDst + i * 16, aSrc + kOff + (sb + i) * 4);
        CP_ASYNC16(bDst + i * 16, bSrc + kOff + (sb + i) * 4);
    }
    CP_COMMIT();
}

// ============================================================
// GEMM1 + SiLU*up. B rows interleaved gate/up. grid = (MAXTILES, I/64), 512 thr
// ============================================================
__global__ __launch_bounds__(NTHREADS)
void gemm1_mma(const float* __restrict__ w13) {
    const int tile_m = blockIdx.x;
    if (tile_m >= g_num_tiles) return;
    const int e   = g_tile_expert[tile_m];
    const int nbJ = blockIdx.y * 64;

    extern __shared__ float sm[];

    const int tid = threadIdx.x;
    const int wid = tid >> 5, lid = tid & 31;
    FragCtx f = { wid & 3, wid >> 2, lid >> 2, lid & 3 };

    const int r  = tid >> 2;            // 0..127
    const int sb = (tid & 3) * 4;       // segs 0,4,8,12
    const int tokr = g_token_of_slot[tile_m * BM + r];
    const float* aSrc = g_x32 + (size_t)(tokr < 0 ? 0 : tokr) * H_DIM;
    const int j = r >> 1;
    const int wrow = (r & 1) ? (I_DIM + nbJ + j) : (nbJ + j);
    const float* bSrc = w13 + ((size_t)e * 2 * I_DIM + wrow) * H_DIM;

    const uint32_t smBase = smem_u32(sm);
    uint32_t aDst[NSTAGE], bDst[NSTAGE];
#pragma unroll
    for (int s = 0; s < NSTAGE; s++) {
        aDst[s] = smBase + (s * STAGE_WORDS + r * SM_STRIDE) * 4 + sb * 16;
        bDst[s] = smBase + (s * STAGE_WORDS + A_WORDS + r * SM_STRIDE) * 4 + sb * 16;
    }

    float acc[2][4][4];
#pragma unroll
    for (int a = 0; a < 2; a++)
#pragma unroll
        for (int b = 0; b < 4; b++)
#pragma unroll
            for (int c = 0; c < 4; c++) acc[a][b][c] = 0.f;

    const int NC = H_DIM / BK;   // 32
    issue_chunk(aDst[0], bDst[0], aSrc, bSrc, 0, sb);
    issue_chunk(aDst[1], bDst[1], aSrc, bSrc, BK, sb);

    int stage = 0, stage2 = 2;
#pragma unroll 1
    for (int c = 0; c < NC; c++) {
        if (c + 1 < NC) CP_WAIT(1); else CP_WAIT(0);
        __syncthreads();
        if (c + 2 < NC)
            issue_chunk(aDst[stage2], bDst[stage2], aSrc, bSrc, (c + 2) * BK, sb);
        mma_chunk(sm + stage * STAGE_WORDS, sm + stage * STAGE_WORDS + A_WORDS, f, acc);
        stage = (stage + 1 == NSTAGE) ? 0 : stage + 1;
        stage2 = (stage2 + 1 == NSTAGE) ? 0 : stage2 + 1;
    }

    // epilogue: silu(gate)*up, stored tf32-pre-rounded (same as gemm2's cvt would do)
#pragma unroll
    for (int mf = 0; mf < 2; mf++) {
#pragma unroll
        for (int half = 0; half < 2; half++) {
            const int slot = tile_m * BM + f.wm * 32 + mf * 16 + f.g + half * 8;
            if (g_token_of_slot[slot] >= 0) {
                float* dst = g_act + (size_t)slot * I_DIM + nbJ;
#pragma unroll
                for (int nf = 0; nf < 4; nf++) {
                    const int jj = f.wn * 16 + nf * 4 + f.tg;
                    const float gt = acc[mf][nf][half * 2 + 0];
                    const float up = acc[mf][nf][half * 2 + 1];
                    dst[jj] = __uint_as_float(f2tf32(up * gt / (1.f + expf(-gt))));
                }
            }
        }
    }
}

// ============================================================
// GEMM2 + weighted atomic scatter. grid = (MAXTILES, H/128), 512 thr
// ============================================================
__global__ __launch_bounds__(NTHREADS)
void gemm2_mma(const float* __restrict__ w2, float* __restrict__ out) {
    const int tile_m = blockIdx.x;
    if (tile_m >= g_num_tiles) return;
    const int e     = g_tile_expert[tile_m];
    const int nbase = blockIdx.y * BN;

    extern __shared__ float sm[];

    const int tid = threadIdx.x;
    const int wid = tid >> 5, lid = tid & 31;
    FragCtx f = { wid & 3, wid >> 2, lid >> 2, lid & 3 };

    const int r  = tid >> 2;
    const int sb = (tid & 3) * 4;
    const float* aSrc = g_act + (size_t)(tile_m * BM + r) * I_DIM;   // pad rows stay 0
    const float* bSrc = w2 + ((size_t)e * H_DIM + (nbase + r)) * I_DIM;

    const uint32_t smBase = smem_u32(sm);
    uint32_t aDst[NSTAGE], bDst[NSTAGE];
#pragma unroll
    for (int s = 0; s < NSTAGE; s++) {
        aDst[s] = smBase + (s * STAGE_WORDS + r * SM_STRIDE) * 4 + sb * 16;
        bDst[s] = smBase + (s * STAGE_WORDS + A_WORDS + r * SM_STRIDE) * 4 + sb * 16;
    }

    float acc[2][4][4];
#pragma unroll
    for (int a = 0; a < 2; a++)
#pragma unroll
        for (int b = 0; b < 4; b++)
#pragma unroll
            for (int c = 0; c < 4; c++) acc[a][b][c] = 0.f;

    const int NC = I_DIM / BK;   // 22
    issue_chunk(aDst[0], bDst[0], aSrc, bSrc, 0, sb);
    issue_chunk(aDst[1], bDst[1], aSrc, bSrc, BK, sb);

    int stage = 0, stage2 = 2;
#pragma unroll 1
    for (int c = 0; c < NC; c++) {
        if (c + 1 < NC) CP_WAIT(1); else CP_WAIT(0);
        __syncthreads();
        if (c + 2 < NC)
            issue_chunk(aDst[stage2], bDst[stage2], aSrc, bSrc, (c + 2) * BK, sb);
        mma_chunk(sm + stage * STAGE_WORDS, sm + stage * STAGE_WORDS + A_WORDS, f, acc);
        stage = (stage + 1 == NSTAGE) ? 0 : stage + 1;
        stage2 = (stage2 + 1 == NSTAGE) ? 0 : stage2 + 1;
    }

#pragma unroll
    for (int mf = 0; mf < 2; mf++) {
#pragma unroll
        for (int half = 0; half < 2; half++) {
            const int slot = tile_m * BM + f.wm * 32 + mf * 16 + f.g + half * 8;
            const int tok  = g_token_of_slot[slot];
            if (tok >= 0) {
                const float w = g_slot_weight[slot];
                float* dst = out + (size_t)tok * H_DIM + nbase;
#pragma unroll
                for (int nf = 0; nf < 4; nf++) {
                    const int col = f.wn * 32 + nf * 8 + f.tg * 2;
                    atomicAdd(&dst[col],     w * acc[mf][nf][half * 2 + 0]);
                    atomicAdd(&dst[col + 1], w * acc[mf][nf][half * 2 + 1]);
                }
            }
        }
    }
}

// ============================================================
extern "C" void kernel_launch(void* const* d_in, const int* in_sizes, int n_in,
                              void* d_out, int out_size) {
    const float* x      = (const float*)d_in[0];   // [1024, 2048]
    const float* logits = (const float*)d_in[1];   // [1024, 8]
    const float* w13    = (const float*)d_in[2];   // [8, 2816, 2048]
    const float* w2     = (const float*)d_in[3];   // [8, 2048, 1408]
    float* out = (float*)d_out;                    // [1024, 2048]
    (void)in_sizes; (void)n_in;

    cudaFuncSetAttribute(gemm1_mma, cudaFuncAttributeMaxDynamicSharedMemorySize, SMEM_DYN_BYTES);
    cudaFuncSetAttribute(gemm2_mma, cudaFuncAttributeMaxDynamicSharedMemorySize, SMEM_DYN_BYTES);

    cudaMemsetAsync(d_out, 0, (size_t)out_size * sizeof(float));
    convert_x<<<(T_TOK * H_DIM) / (256 * 4), 256>>>(x);
    routing_kernel<<<1, 1024>>>(logits);
    gemm1_mma<<<dim3(MAXTILES, I_DIM / 64), NTHREADS, SMEM_DYN_BYTES>>>(w13);
    gemm2_mma<<<dim3(MAXTILES, H_DIM / BN), NTHREADS, SMEM_DYN_BYTES>>>(w2, out);
}

// round 11
// speedup vs baseline: 1.8553x; 1.8553x over previous
#include <cuda_runtime.h>
#include <cuda_fp16.h>
#include <cstdint>
#include <math.h>

// ---------------- problem constants ----------------
#define T_TOK 1024
#define H_DIM 2048
#define I_DIM 1408
#define N_EXP 8

// ---------------- tiling ----------------
#define BM 128
#define BN 128
#define BK 32            // halves per chunk row
#define NSTAGE 4
#define MAXSLOT  3072
#define MAXTILES 24
#define NTHREADS 512

#define ROW_H 40                                  // halves per smem row (80 B, conflict-free)
#define A_HALVES (BM * ROW_H)                     // 5120 halves = 10 KB
#define STAGE_HALVES (2 * A_HALVES)               // A+B = 20 KB
#define STAGE_BYTES (STAGE_HALVES * 2)
#define SMEM_DYN_BYTES (NSTAGE * STAGE_BYTES)     // 80 KB -> 2 blocks/SM

// ---------------- scratch (static; ~151 MB total) ----------------
__device__ int    g_token_of_slot[MAXSLOT];
__device__ float  g_slot_weight[MAXSLOT];
__device__ int    g_tile_expert[MAXTILES];
__device__ int    g_num_tiles;
__device__ __half g_act[(size_t)MAXSLOT * I_DIM];                 // 8.7 MB
__device__ __half g_xh[(size_t)T_TOK * H_DIM];                    // 4 MB
__device__ __half g_wh13[(size_t)N_EXP * 2 * I_DIM * H_DIM];      // 92.3 MB
__device__ __half g_wh2[(size_t)N_EXP * H_DIM * I_DIM];           // 46.2 MB

// ---------------- PTX helpers (baseline sm_80+; nothing 'a'-gated) ----------------
__device__ __forceinline__ uint32_t smem_u32(const void* p) {
    uint32_t a;
    asm("{ .reg .u64 t; cvta.to.shared.u64 t, %1; cvt.u32.u64 %0, t; }" : "=r"(a) : "l"(p));
    return a;
}
#define CP_ASYNC16(dst_u32, src_ptr) \
    asm volatile("cp.async.cg.shared.global [%0], [%1], 16;" :: "r"(dst_u32), "l"(src_ptr))
#define CP_COMMIT()  asm volatile("cp.async.commit_group;" ::: "memory")
#define CP_WAIT(N)   asm volatile("cp.async.wait_group %0;" :: "n"(N) : "memory")

__device__ __forceinline__ void mma_f16(float* c, const uint32_t* a, const uint32_t* b) {
    asm volatile(
        "mma.sync.aligned.m16n8k16.row.col.f32.f16.f16.f32 "
        "{%0,%1,%2,%3}, {%4,%5,%6,%7}, {%8,%9}, {%0,%1,%2,%3};"
        : "+f"(c[0]), "+f"(c[1]), "+f"(c[2]), "+f"(c[3])
        : "r"(a[0]), "r"(a[1]), "r"(a[2]), "r"(a[3]), "r"(b[0]), "r"(b[1]));
}

// ============================================================
// fp32 -> fp16 conversion kernels (one float4 -> uint2 per thread)
// ============================================================
__device__ __forceinline__ uint2 cvt4(float4 v) {
    __half2 h01 = __floats2half2_rn(v.x, v.y);   // low = x (even k at lower addr)
    __half2 h23 = __floats2half2_rn(v.z, v.w);
    uint2 o;
    o.x = *reinterpret_cast<uint32_t*>(&h01);
    o.y = *reinterpret_cast<uint32_t*>(&h23);
    return o;
}
__global__ void conv_w13(const float4* __restrict__ src) {
    size_t i = (size_t)blockIdx.x * 256 + threadIdx.x;
    ((uint2*)g_wh13)[i] = cvt4(src[i]);
}
__global__ void conv_w2(const float4* __restrict__ src) {
    size_t i = (size_t)blockIdx.x * 256 + threadIdx.x;
    ((uint2*)g_wh2)[i] = cvt4(src[i]);
}
__global__ void conv_x(const float4* __restrict__ src) {
    size_t i = (size_t)blockIdx.x * 256 + threadIdx.x;
    ((uint2*)g_xh)[i] = cvt4(src[i]);
}

// ============================================================
// Routing: softmax -> top2 -> renormalize; padded per-expert slot lists (x128).
// ============================================================
__global__ void routing_kernel(const float* __restrict__ logits) {
    __shared__ int s_cnt[N_EXP];
    __shared__ int s_cur[N_EXP];
    __shared__ int s_off[N_EXP + 1];

    const int t = threadIdx.x;
    if (t < N_EXP) { s_cnt[t] = 0; s_cur[t] = 0; }
    for (int s = t; s < MAXSLOT; s += blockDim.x) g_token_of_slot[s] = -1;
    __syncthreads();

    int e1 = 0, e2 = 0;
    float w1 = 0.f, w2 = 0.f;
    if (t < T_TOK) {
        float l[N_EXP];
#pragma unroll
        for (int e = 0; e < N_EXP; e++) l[e] = logits[t * N_EXP + e];
        float b1 = -1e30f;
#pragma unroll
        for (int e = 0; e < N_EXP; e++) if (l[e] > b1) { b1 = l[e]; e1 = e; }
        float b2 = -1e30f;
        e2 = (e1 == 0) ? 1 : 0;
#pragma unroll
        for (int e = 0; e < N_EXP; e++) if (e != e1 && l[e] > b2) { b2 = l[e]; e2 = e; }
        float p2 = expf(b2 - b1);
        w1 = 1.f / (1.f + p2);
        w2 = p2 / (1.f + p2);
        atomicAdd(&s_cnt[e1], 1);
        atomicAdd(&s_cnt[e2], 1);
    }
    __syncthreads();

    if (t == 0) {
        int off = 0;
        for (int e = 0; e < N_EXP; e++) {
            s_off[e] = off;
            int tiles = (s_cnt[e] + BM - 1) / BM;
            for (int i = 0; i < tiles; i++) g_tile_expert[off / BM + i] = e;
            off += tiles * BM;
        }
        s_off[N_EXP] = off;
        g_num_tiles = off / BM;
    }
    __syncthreads();

    if (t < T_TOK) {
        int p = atomicAdd(&s_cur[e1], 1);
        int s = s_off[e1] + p;
        g_token_of_slot[s] = t;
        g_slot_weight[s]   = w1;
        p = atomicAdd(&s_cur[e2], 1);
        s = s_off[e2] + p;
        g_token_of_slot[s] = t;
        g_slot_weight[s]   = w2;
    }
}

// ============================================================
// Fragments: 16 warps, wm = wid&3 (32 rows), wn = wid>>2 (32 cols).
// Warp tile 32x32; fp16 m16n8k16; fragments are direct u32 LDS (no cvt!).
// Chunk k32 = 2 k16 steps. Row stride 20 u32 (banks (g*20+tg)%32 all distinct).
// ============================================================
struct FragCtx { int wm, wn, g, tg; };

__device__ __forceinline__ void mma_chunk(const uint32_t* __restrict__ Au,
                                          const uint32_t* __restrict__ Bu,
                                          const FragCtx& f,
                                          float acc[2][4][4]) {
#pragma unroll
    for (int ks = 0; ks < 2; ks++) {
        uint32_t af[2][4];
#pragma unroll
        for (int mf = 0; mf < 2; mf++) {
            const int base = (f.wm * 32 + mf * 16 + f.g) * (ROW_H / 2) + ks * 8 + f.tg;
            af[mf][0] = Au[base];
            af[mf][1] = Au[base + 8 * (ROW_H / 2)];
            af[mf][2] = Au[base + 4];
            af[mf][3] = Au[base + 8 * (ROW_H / 2) + 4];
        }
        uint32_t bf[4][2];
#pragma unroll
        for (int nf = 0; nf < 4; nf++) {
            const int bb = (f.wn * 32 + nf * 8 + f.g) * (ROW_H / 2) + ks * 8 + f.tg;
            bf[nf][0] = Bu[bb];
            bf[nf][1] = Bu[bb + 4];
        }
#pragma unroll
        for (int mf = 0; mf < 2; mf++)
#pragma unroll
            for (int nf = 0; nf < 4; nf++)
                mma_f16(acc[mf][nf], af[mf], bf[nf]);
    }
}

// loaders: each thread 1 A seg + 1 B seg of 16B (8 halves); 512 thr = 128 rows x 4 segs
__device__ __forceinline__ void issue_chunk(uint32_t aDst, uint32_t bDst,
                                            const __half* aSrc, const __half* bSrc,
                                            int kOff, int sb) {
    CP_ASYNC16(aDst, aSrc + kOff + sb * 8);
    CP_ASYNC16(bDst, bSrc + kOff + sb * 8);
    CP_COMMIT();
}

// ============================================================
// GEMM1 + SiLU*up. B rows interleaved gate/up. grid = (MAXTILES, I/64)
// ============================================================
__global__ __launch_bounds__(NTHREADS, 2)
void gemm1_mma(void) {
    const int tile_m = blockIdx.x;
    if (tile_m >= g_num_tiles) return;
    const int e   = g_tile_expert[tile_m];
    const int nbJ = blockIdx.y * 64;

    extern __shared__ __half smh[];

    const int tid = threadIdx.x;
    const int wid = tid >> 5, lid = tid & 31;
    FragCtx f = { wid & 3, wid >> 2, lid >> 2, lid & 3 };

    const int r  = tid >> 2;            // 0..127
    const int sb = tid & 3;             // seg 0..3
    const int tokr = g_token_of_slot[tile_m * BM + r];
    const __half* aSrc = g_xh + (size_t)(tokr < 0 ? 0 : tokr) * H_DIM;
    const int j = r >> 1;
    const int wrow = (r & 1) ? (I_DIM + nbJ + j) : (nbJ + j);
    const __half* bSrc = g_wh13 + ((size_t)e * 2 * I_DIM + wrow) * H_DIM;

    const uint32_t smBase = smem_u32(smh);
    uint32_t aDst[NSTAGE], bDst[NSTAGE];
#pragma unroll
    for (int s = 0; s < NSTAGE; s++) {
        aDst[s] = smBase + s * STAGE_BYTES + r * (ROW_H * 2) + sb * 16;
        bDst[s] = aDst[s] + A_HALVES * 2;
    }

    float acc[2][4][4];
#pragma unroll
    for (int a = 0; a < 2; a++)
#pragma unroll
        for (int b = 0; b < 4; b++)
#pragma unroll
            for (int c = 0; c < 4; c++) acc[a][b][c] = 0.f;

    const int NC = H_DIM / BK;   // 64
    issue_chunk(aDst[0], bDst[0], aSrc, bSrc, 0 * BK, sb);
    issue_chunk(aDst[1], bDst[1], aSrc, bSrc, 1 * BK, sb);
    issue_chunk(aDst[2], bDst[2], aSrc, bSrc, 2 * BK, sb);

#pragma unroll 1
    for (int c = 0; c < NC; c++) {
        if (c + 2 < NC)      CP_WAIT(2);
        else if (c + 1 < NC) CP_WAIT(1);
        else                 CP_WAIT(0);
        __syncthreads();
        if (c + 3 < NC) {
            const int ns = (c + 3) & 3;
            issue_chunk(aDst[ns], bDst[ns], aSrc, bSrc, (c + 3) * BK, sb);
        }
        const int st = c & 3;
        mma_chunk((const uint32_t*)(smh + st * STAGE_HALVES),
                  (const uint32_t*)(smh + st * STAGE_HALVES + A_HALVES), f, acc);
    }

    // epilogue: silu(gate)*up; c-pair (even,odd) = (gate, up) of same col; store fp16
#pragma unroll
    for (int mf = 0; mf < 2; mf++) {
#pragma unroll
        for (int half = 0; half < 2; half++) {
            const int slot = tile_m * BM + f.wm * 32 + mf * 16 + f.g + half * 8;
            if (g_token_of_slot[slot] >= 0) {
                __half* dst = g_act + (size_t)slot * I_DIM + nbJ;
#pragma unroll
                for (int nf = 0; nf < 4; nf++) {
                    const int jj = f.wn * 16 + nf * 4 + f.tg;
                    const float gt = acc[mf][nf][half * 2 + 0];
                    const float up = acc[mf][nf][half * 2 + 1];
                    dst[jj] = __float2half_rn(up * gt / (1.f + expf(-gt)));
                }
            }
        }
    }
}

// ============================================================
// GEMM2 + weighted atomic scatter. grid = (MAXTILES, H/128)
// ============================================================
__global__ __launch_bounds__(NTHREADS, 2)
void gemm2_mma(float* __restrict__ out) {
    const int tile_m = blockIdx.x;
    if (tile_m >= g_num_tiles) return;
    const int e     = g_tile_expert[tile_m];
    const int nbase = blockIdx.y * BN;

    extern __shared__ __half smh[];

    const int tid = threadIdx.x;
    const int wid = tid >> 5, lid = tid & 31;
    FragCtx f = { wid & 3, wid >> 2, lid >> 2, lid & 3 };

    const int r  = tid >> 2;
    const int sb = tid & 3;
    const __half* aSrc = g_act + (size_t)(tile_m * BM + r) * I_DIM;  // pad rows: finite garbage, rows discarded
    const __half* bSrc = g_wh2 + ((size_t)e * H_DIM + (nbase + r)) * I_DIM;

    const uint32_t smBase = smem_u32(smh);
    uint32_t aDst[NSTAGE], bDst[NSTAGE];
#pragma unroll
    for (int s = 0; s < NSTAGE; s++) {
        aDst[s] = smBase + s * STAGE_BYTES + r * (ROW_H * 2) + sb * 16;
        bDst[s] = aDst[s] + A_HALVES * 2;
    }

    float acc[2][4][4];
#pragma unroll
    for (int a = 0; a < 2; a++)
#pragma unroll
        for (int b = 0; b < 4; b++)
#pragma unroll
            for (int c = 0; c < 4; c++) acc[a][b][c] = 0.f;

    const int NC = I_DIM / BK;   // 44
    issue_chunk(aDst[0], bDst[0], aSrc, bSrc, 0 * BK, sb);
    issue_chunk(aDst[1], bDst[1], aSrc, bSrc, 1 * BK, sb);
    issue_chunk(aDst[2], bDst[2], aSrc, bSrc, 2 * BK, sb);

#pragma unroll 1
    for (int c = 0; c < NC; c++) {
        if (c + 2 < NC)      CP_WAIT(2);
        else if (c + 1 < NC) CP_WAIT(1);
        else                 CP_WAIT(0);
        __syncthreads();
        if (c + 3 < NC) {
            const int ns = (c + 3) & 3;
            issue_chunk(aDst[ns], bDst[ns], aSrc, bSrc, (c + 3) * BK, sb);
        }
        const int st = c & 3;
        mma_chunk((const uint32_t*)(smh + st * STAGE_HALVES),
                  (const uint32_t*)(smh + st * STAGE_HALVES + A_HALVES), f, acc);
    }

#pragma unroll
    for (int mf = 0; mf < 2; mf++) {
#pragma unroll
        for (int half = 0; half < 2; half++) {
            const int slot = tile_m * BM + f.wm * 32 + mf * 16 + f.g + half * 8;
            const int tok  = g_token_of_slot[slot];
            if (tok >= 0) {
                const float w = g_slot_weight[slot];
                float* dst = out + (size_t)tok * H_DIM + nbase;
#pragma unroll
                for (int nf = 0; nf < 4; nf++) {
                    const int col = f.wn * 32 + nf * 8 + f.tg * 2;
                    atomicAdd(&dst[col],     w * acc[mf][nf][half * 2 + 0]);
                    atomicAdd(&dst[col + 1], w * acc[mf][nf][half * 2 + 1]);
                }
            }
        }
    }
}

// ============================================================
extern "C" void kernel_launch(void* const* d_in, const int* in_sizes, int n_in,
                              void* d_out, int out_size) {
    const float* x      = (const float*)d_in[0];   // [1024, 2048]
    const float* logits = (const float*)d_in[1];   // [1024, 8]
    const float* w13    = (const float*)d_in[2];   // [8, 2816, 2048]
    const float* w2     = (const float*)d_in[3];   // [8, 2048, 1408]
    float* out = (float*)d_out;                    // [1024, 2048]
    (void)in_sizes; (void)n_in;

    cudaFuncSetAttribute(gemm1_mma, cudaFuncAttributeMaxDynamicSharedMemorySize, SMEM_DYN_BYTES);
    cudaFuncSetAttribute(gemm2_mma, cudaFuncAttributeMaxDynamicSharedMemorySize, SMEM_DYN_BYTES);

    cudaMemsetAsync(d_out, 0, (size_t)out_size * sizeof(float));
    conv_x  <<<(T_TOK * H_DIM) / 1024, 256>>>((const float4*)x);
    conv_w13<<<(N_EXP * 2 * I_DIM * H_DIM) / 1024, 256>>>((const float4*)w13);
    conv_w2 <<<(N_EXP * H_DIM * I_DIM) / 1024, 256>>>((const float4*)w2);
    routing_kernel<<<1, 1024>>>(logits);
    gemm1_mma<<<dim3(MAXTILES, I_DIM / 64), NTHREADS, SMEM_DYN_BYTES>>>();
    gemm2_mma<<<dim3(MAXTILES, H_DIM / BN), NTHREADS, SMEM_DYN_BYTES>>>(out);
}

// round 12
// speedup vs baseline: 1.8856x; 1.0163x over previous
#include <cuda_runtime.h>
#include <cuda_fp16.h>
#include <cstdint>
#include <math.h>

// ---------------- problem constants ----------------
#define T_TOK 1024
#define H_DIM 2048
#define I_DIM 1408
#define N_EXP 8

// ---------------- tiling ----------------
#define BM 128
#define BN 128
#define BK 32            // halves per chunk row
#define NSTAGE 4
#define MAXSLOT  3072
#define MAXTILES 24
#define NTHREADS 512

#define ROW_H 40                                  // halves per smem row (80 B, conflict-free)
#define ROW_B (ROW_H * 2)                         // 80 bytes
#define A_HALVES (BM * ROW_H)                     // 5120 halves = 10 KB
#define STAGE_HALVES (2 * A_HALVES)               // A+B = 20 KB
#define STAGE_BYTES (STAGE_HALVES * 2)
#define SMEM_DYN_BYTES (NSTAGE * STAGE_BYTES)     // 80 KB -> 2 blocks/SM

// ---------------- scratch (static; ~151 MB total) ----------------
__device__ int    g_token_of_slot[MAXSLOT];
__device__ float  g_slot_weight[MAXSLOT];
__device__ int    g_tile_expert[MAXTILES];
__device__ int    g_num_tiles;
__device__ __half g_act[(size_t)MAXSLOT * I_DIM];                 // 8.7 MB
__device__ __half g_xh[(size_t)T_TOK * H_DIM];                    // 4 MB
__device__ __half g_wh13[(size_t)N_EXP * 2 * I_DIM * H_DIM];      // 92.3 MB
__device__ __half g_wh2[(size_t)N_EXP * H_DIM * I_DIM];           // 46.2 MB

// ---------------- PTX helpers (baseline sm_80+; nothing 'a'-gated) ----------------
__device__ __forceinline__ uint32_t smem_u32(const void* p) {
    uint32_t a;
    asm("{ .reg .u64 t; cvta.to.shared.u64 t, %1; cvt.u32.u64 %0, t; }" : "=r"(a) : "l"(p));
    return a;
}
#define CP_ASYNC16(dst_u32, src_ptr) \
    asm volatile("cp.async.cg.shared.global [%0], [%1], 16;" :: "r"(dst_u32), "l"(src_ptr))
#define CP_COMMIT()  asm volatile("cp.async.commit_group;" ::: "memory")
#define CP_WAIT(N)   asm volatile("cp.async.wait_group %0;" :: "n"(N) : "memory")

#define LDSM_X4(r0, r1, r2, r3, addr) \
    asm volatile("ldmatrix.sync.aligned.m8n8.x4.shared.b16 {%0,%1,%2,%3}, [%4];" \
        : "=r"(r0), "=r"(r1), "=r"(r2), "=r"(r3) : "r"(addr))

__device__ __forceinline__ void mma_f16(float* c, const uint32_t* a, const uint32_t* b) {
    asm volatile(
        "mma.sync.aligned.m16n8k16.row.col.f32.f16.f16.f32 "
        "{%0,%1,%2,%3}, {%4,%5,%6,%7}, {%8,%9}, {%0,%1,%2,%3};"
        : "+f"(c[0]), "+f"(c[1]), "+f"(c[2]), "+f"(c[3])
        : "r"(a[0]), "r"(a[1]), "r"(a[2]), "r"(a[3]), "r"(b[0]), "r"(b[1]));
}

// ============================================================
// fp32 -> fp16 conversion kernels
// ============================================================
__device__ __forceinline__ uint2 cvt4(float4 v) {
    __half2 h01 = __floats2half2_rn(v.x, v.y);   // low half = x (even k at lower addr)
    __half2 h23 = __floats2half2_rn(v.z, v.w);
    uint2 o;
    o.x = *reinterpret_cast<uint32_t*>(&h01);
    o.y = *reinterpret_cast<uint32_t*>(&h23);
    return o;
}
__global__ void conv_w13(const float4* __restrict__ src) {
    size_t i = (size_t)blockIdx.x * 256 + threadIdx.x;
    ((uint2*)g_wh13)[i] = cvt4(src[i]);
}
__global__ void conv_w2(const float4* __restrict__ src) {
    size_t i = (size_t)blockIdx.x * 256 + threadIdx.x;
    ((uint2*)g_wh2)[i] = cvt4(src[i]);
}
__global__ void conv_x(const float4* __restrict__ src) {
    size_t i = (size_t)blockIdx.x * 256 + threadIdx.x;
    ((uint2*)g_xh)[i] = cvt4(src[i]);
}

// ============================================================
// Routing: softmax -> top2 -> renormalize; padded per-expert slot lists (x128).
// ============================================================
__global__ void routing_kernel(const float* __restrict__ logits) {
    __shared__ int s_cnt[N_EXP];
    __shared__ int s_cur[N_EXP];
    __shared__ int s_off[N_EXP + 1];

    const int t = threadIdx.x;
    if (t < N_EXP) { s_cnt[t] = 0; s_cur[t] = 0; }
    for (int s = t; s < MAXSLOT; s += blockDim.x) g_token_of_slot[s] = -1;
    __syncthreads();

    int e1 = 0, e2 = 0;
    float w1 = 0.f, w2 = 0.f;
    if (t < T_TOK) {
        float l[N_EXP];
#pragma unroll
        for (int e = 0; e < N_EXP; e++) l[e] = logits[t * N_EXP + e];
        float b1 = -1e30f;
#pragma unroll
        for (int e = 0; e < N_EXP; e++) if (l[e] > b1) { b1 = l[e]; e1 = e; }
        float b2 = -1e30f;
        e2 = (e1 == 0) ? 1 : 0;
#pragma unroll
        for (int e = 0; e < N_EXP; e++) if (e != e1 && l[e] > b2) { b2 = l[e]; e2 = e; }
        float p2 = expf(b2 - b1);
        w1 = 1.f / (1.f + p2);
        w2 = p2 / (1.f + p2);
        atomicAdd(&s_cnt[e1], 1);
        atomicAdd(&s_cnt[e2], 1);
    }
    __syncthreads();

    if (t == 0) {
        int off = 0;
        for (int e = 0; e < N_EXP; e++) {
            s_off[e] = off;
            int tiles = (s_cnt[e] + BM - 1) / BM;
            for (int i = 0; i < tiles; i++) g_tile_expert[off / BM + i] = e;
            off += tiles * BM;
        }
        s_off[N_EXP] = off;
        g_num_tiles = off / BM;
    }
    __syncthreads();

    if (t < T_TOK) {
        int p = atomicAdd(&s_cur[e1], 1);
        int s = s_off[e1] + p;
        g_token_of_slot[s] = t;
        g_slot_weight[s]   = w1;
        p = atomicAdd(&s_cur[e2], 1);
        s = s_off[e2] + p;
        g_token_of_slot[s] = t;
        g_slot_weight[s]   = w2;
    }
}

// ============================================================
// Fragments via ldmatrix.x4.
// 16 warps: wm = wid&3 (32 rows), wn = wid>>2 (32 cols); warp tile 32x32.
// A addr (mf,ks): row = wm*32+mf*16+(lid%16); kbyte = ks*32 + (lid/16)*16
//   -> regs a0..a3 in mma order (m0-7/klo, m8-15/klo, m0-7/khi, m8-15/khi).
// B addr (np,ks): n = wn*32+np*16+(lid/16)*8+(lid%8); kbyte = ks*32 + ((lid/8)&1)*16
//   -> regs = {bf[2np][0], bf[2np][1], bf[2np+1][0], bf[2np+1][1]}.
// ============================================================
struct FragAddr {
    uint32_t a[2][2];   // [mf][ks] stage-0 smem byte addresses
    uint32_t b[2][2];   // [np][ks]
};

__device__ __forceinline__ FragAddr make_frag_addrs(uint32_t smBase, int wid, int lid) {
    FragAddr fa;
    const int wm = wid & 3, wn = wid >> 2;
#pragma unroll
    for (int mf = 0; mf < 2; mf++)
#pragma unroll
        for (int ks = 0; ks < 2; ks++) {
            const int row = wm * 32 + mf * 16 + (lid & 15);
            fa.a[mf][ks] = smBase + row * ROW_B + ks * 32 + (lid >> 4) * 16;
        }
#pragma unroll
    for (int np = 0; np < 2; np++)
#pragma unroll
        for (int ks = 0; ks < 2; ks++) {
            const int n = wn * 32 + np * 16 + ((lid >> 4) * 8) + (lid & 7);
            fa.b[np][ks] = smBase + A_HALVES * 2 + n * ROW_B + ks * 32 + ((lid >> 3) & 1) * 16;
        }
    return fa;
}

__device__ __forceinline__ void mma_chunk(const FragAddr& fa, uint32_t stOff,
                                          float acc[2][4][4]) {
#pragma unroll
    for (int ks = 0; ks < 2; ks++) {
        uint32_t af[2][4];
#pragma unroll
        for (int mf = 0; mf < 2; mf++)
            LDSM_X4(af[mf][0], af[mf][1], af[mf][2], af[mf][3], fa.a[mf][ks] + stOff);
        uint32_t bf[4][2];
#pragma unroll
        for (int np = 0; np < 2; np++)
            LDSM_X4(bf[2 * np][0], bf[2 * np][1], bf[2 * np + 1][0], bf[2 * np + 1][1],
                    fa.b[np][ks] + stOff);
#pragma unroll
        for (int mf = 0; mf < 2; mf++)
#pragma unroll
            for (int nf = 0; nf < 4; nf++)
                mma_f16(acc[mf][nf], af[mf], bf[nf]);
    }
}

// loaders: each thread 1 A seg + 1 B seg of 16B; 512 thr = 128 rows x 4 segs
__device__ __forceinline__ void issue_chunk(uint32_t aDst, uint32_t bDst,
                                            const __half* aSrc, const __half* bSrc,
                                            int kOff, int sb) {
    CP_ASYNC16(aDst, aSrc + kOff + sb * 8);
    CP_ASYNC16(bDst, bSrc + kOff + sb * 8);
    CP_COMMIT();
}

// ============================================================
// GEMM1 + SiLU*up. B rows interleaved gate/up. grid = (MAXTILES, I/64)
// ============================================================
__global__ __launch_bounds__(NTHREADS, 2)
void gemm1_mma(void) {
    const int tile_m = blockIdx.x;
    if (tile_m >= g_num_tiles) return;
    const int e   = g_tile_expert[tile_m];
    const int nbJ = blockIdx.y * 64;

    extern __shared__ __half smh[];

    const int tid = threadIdx.x;
    const int wid = tid >> 5, lid = tid & 31;
    const int fg = lid >> 2, ftg = lid & 3;
    const int fwm = wid & 3, fwn = wid >> 2;

    const int r  = tid >> 2;            // 0..127
    const int sb = tid & 3;             // seg 0..3
    const int tokr = g_token_of_slot[tile_m * BM + r];
    const __half* aSrc = g_xh + (size_t)(tokr < 0 ? 0 : tokr) * H_DIM;
    const int j = r >> 1;
    const int wrow = (r & 1) ? (I_DIM + nbJ + j) : (nbJ + j);
    const __half* bSrc = g_wh13 + ((size_t)e * 2 * I_DIM + wrow) * H_DIM;

    const uint32_t smBase = smem_u32(smh);
    const FragAddr fa = make_frag_addrs(smBase, wid, lid);
    uint32_t aDst[NSTAGE], bDst[NSTAGE];
#pragma unroll
    for (int s = 0; s < NSTAGE; s++) {
        aDst[s] = smBase + s * STAGE_BYTES + r * ROW_B + sb * 16;
        bDst[s] = aDst[s] + A_HALVES * 2;
    }

    float acc[2][4][4];
#pragma unroll
    for (int a = 0; a < 2; a++)
#pragma unroll
        for (int b = 0; b < 4; b++)
#pragma unroll
            for (int c = 0; c < 4; c++) acc[a][b][c] = 0.f;

    const int NC = H_DIM / BK;   // 64
    issue_chunk(aDst[0], bDst[0], aSrc, bSrc, 0 * BK, sb);
    issue_chunk(aDst[1], bDst[1], aSrc, bSrc, 1 * BK, sb);
    issue_chunk(aDst[2], bDst[2], aSrc, bSrc, 2 * BK, sb);

#pragma unroll 1
    for (int c = 0; c < NC; c++) {
        if (c + 2 < NC)      CP_WAIT(2);
        else if (c + 1 < NC) CP_WAIT(1);
        else                 CP_WAIT(0);
        __syncthreads();
        if (c + 3 < NC) {
            const int ns = (c + 3) & 3;
            issue_chunk(aDst[ns], bDst[ns], aSrc, bSrc, (c + 3) * BK, sb);
        }
        mma_chunk(fa, (uint32_t)((c & 3) * STAGE_BYTES), acc);
    }

    // epilogue: silu(gate)*up; c-pair (even,odd) = (gate, up) of same col; store fp16
#pragma unroll
    for (int mf = 0; mf < 2; mf++) {
#pragma unroll
        for (int half = 0; half < 2; half++) {
            const int slot = tile_m * BM + fwm * 32 + mf * 16 + fg + half * 8;
            if (g_token_of_slot[slot] >= 0) {
                __half* dst = g_act + (size_t)slot * I_DIM + nbJ;
#pragma unroll
                for (int nf = 0; nf < 4; nf++) {
                    const int jj = fwn * 16 + nf * 4 + ftg;
                    const float gt = acc[mf][nf][half * 2 + 0];
                    const float up = acc[mf][nf][half * 2 + 1];
                    dst[jj] = __float2half_rn(up * gt / (1.f + expf(-gt)));
                }
            }
        }
    }
}

// ============================================================
// GEMM2 + weighted atomic scatter. grid = (MAXTILES, H/128)
// ============================================================
__global__ __launch_bounds__(NTHREADS, 2)
void gemm2_mma(float* __restrict__ out) {
    const int tile_m = blockIdx.x;
    if (tile_m >= g_num_tiles) return;
    const int e     = g_tile_expert[tile_m];
    const int nbase = blockIdx.y * BN;

    extern __shared__ __half smh[];

    const int tid = threadIdx.x;
    const int wid = tid >> 5, lid = tid & 31;
    const int fg = lid >> 2, ftg = lid & 3;
    const int fwm = wid & 3, fwn = wid >> 2;

    const int r  = tid >> 2;
    const int sb = tid & 3;
    const __half* aSrc = g_act + (size_t)(tile_m * BM + r) * I_DIM;  // pad rows: finite garbage, rows discarded
    const __half* bSrc = g_wh2 + ((size_t)e * H_DIM + (nbase + r)) * I_DIM;

    const uint32_t smBase = smem_u32(smh);
    const FragAddr fa = make_frag_addrs(smBase, wid, lid);
    uint32_t aDst[NSTAGE], bDst[NSTAGE];
#pragma unroll
    for (int s = 0; s < NSTAGE; s++) {
        aDst[s] = smBase + s * STAGE_BYTES + r * ROW_B + sb * 16;
        bDst[s] = aDst[s] + A_HALVES * 2;
    }

    float acc[2][4][4];
#pragma unroll
    for (int a = 0; a < 2; a++)
#pragma unroll
        for (int b = 0; b < 4; b++)
#pragma unroll
            for (int c = 0; c < 4; c++) acc[a][b][c] = 0.f;

    const int NC = I_DIM / BK;   // 44
    issue_chunk(aDst[0], bDst[0], aSrc, bSrc, 0 * BK, sb);
    issue_chunk(aDst[1], bDst[1], aSrc, bSrc, 1 * BK, sb);
    issue_chunk(aDst[2], bDst[2], aSrc, bSrc, 2 * BK, sb);

#pragma unroll 1
    for (int c = 0; c < NC; c++) {
        if (c + 2 < NC)      CP_WAIT(2);
        else if (c + 1 < NC) CP_WAIT(1);
        else                 CP_WAIT(0);
        __syncthreads();
        if (c + 3 < NC) {
            const int ns = (c + 3) & 3;
            issue_chunk(aDst[ns], bDst[ns], aSrc, bSrc, (c + 3) * BK, sb);
        }
        mma_chunk(fa, (uint32_t)((c & 3) * STAGE_BYTES), acc);
    }

#pragma unroll
    for (int mf = 0; mf < 2; mf++) {
#pragma unroll
        for (int half = 0; half < 2; half++) {
            const int slot = tile_m * BM + fwm * 32 + mf * 16 + fg + half * 8;
            const int tok  = g_token_of_slot[slot];
            if (tok >= 0) {
                const float w = g_slot_weight[slot];
                float* dst = out + (size_t)tok * H_DIM + nbase;
#pragma unroll
                for (int nf = 0; nf < 4; nf++) {
                    const int col = fwn * 32 + nf * 8 + ftg * 2;
                    atomicAdd(&dst[col],     w * acc[mf][nf][half * 2 + 0]);
                    atomicAdd(&dst[col + 1], w * acc[mf][nf][half * 2 + 1]);
                }
            }
        }
    }
}

// ============================================================
extern "C" void kernel_launch(void* const* d_in, const int* in_sizes, int n_in,
                              void* d_out, int out_size) {
    const float* x      = (const float*)d_in[0];   // [1024, 2048]
    const float* logits = (const float*)d_in[1];   // [1024, 8]
    const float* w13    = (const float*)d_in[2];   // [8, 2816, 2048]
    const float* w2     = (const float*)d_in[3];   // [8, 2048, 1408]
    float* out = (float*)d_out;                    // [1024, 2048]
    (void)in_sizes; (void)n_in;

    cudaFuncSetAttribute(gemm1_mma, cudaFuncAttributeMaxDynamicSharedMemorySize, SMEM_DYN_BYTES);
    cudaFuncSetAttribute(gemm2_mma, cudaFuncAttributeMaxDynamicSharedMemorySize, SMEM_DYN_BYTES);

    cudaMemsetAsync(d_out, 0, (size_t)out_size * sizeof(float));
    conv_x  <<<(T_TOK * H_DIM) / 1024, 256>>>((const float4*)x);
    conv_w13<<<(N_EXP * 2 * I_DIM * H_DIM) / 1024, 256>>>((const float4*)w13);
    conv_w2 <<<(N_EXP * H_DIM * I_DIM) / 1024, 256>>>((const float4*)w2);
    routing_kernel<<<1, 1024>>>(logits);
    gemm1_mma<<<dim3(MAXTILES, I_DIM / 64), NTHREADS, SMEM_DYN_BYTES>>>();
    gemm2_mma<<<dim3(MAXTILES, H_DIM / BN), NTHREADS, SMEM_DYN_BYTES>>>(out);
}

// round 13
// speedup vs baseline: 1.9845x; 1.0525x over previous
#include <cuda_runtime.h>
#include <cuda_fp16.h>
#include <cstdint>
#include <math.h>

// ---------------- problem constants ----------------
#define T_TOK 1024
#define H_DIM 2048
#define I_DIM 1408
#define N_EXP 8

// ---------------- tiling ----------------
#define BM 128
#define BN 128
#define BK 64            // halves per chunk row (128 B)
#define NSTAGE 3
#define MAXSLOT  3072
#define MAXTILES 24
#define NTHREADS 512

#define ROW_H 72                                  // halves per smem row (144 B, LDSM conflict-free)
#define ROW_B (ROW_H * 2)
#define A_HALVES (BM * ROW_H)                     // 9216 halves = 18 KB
#define STAGE_HALVES (2 * A_HALVES)               // A+B = 36 KB
#define STAGE_BYTES (STAGE_HALVES * 2)
#define SMEM_DYN_BYTES (NSTAGE * STAGE_BYTES)     // 108 KB -> 2 blocks/SM

// ---------------- scratch (static; ~151 MB total) ----------------
__device__ int    g_token_of_slot[MAXSLOT];
__device__ float  g_slot_weight[MAXSLOT];
__device__ int    g_tile_expert[MAXTILES];
__device__ int    g_num_tiles;
__device__ __half g_act[(size_t)MAXSLOT * I_DIM];                 // 8.7 MB
__device__ __half g_xh[(size_t)T_TOK * H_DIM];                    // 4 MB
__device__ __half g_wh13[(size_t)N_EXP * 2 * I_DIM * H_DIM];      // 92.3 MB
__device__ __half g_wh2[(size_t)N_EXP * H_DIM * I_DIM];           // 46.2 MB

// ---------------- PTX helpers (baseline sm_80/90; nothing 'a'-gated) ----------------
__device__ __forceinline__ uint32_t smem_u32(const void* p) {
    uint32_t a;
    asm("{ .reg .u64 t; cvta.to.shared.u64 t, %1; cvt.u32.u64 %0, t; }" : "=r"(a) : "l"(p));
    return a;
}
#define CP_ASYNC16(dst_u32, src_ptr) \
    asm volatile("cp.async.cg.shared.global [%0], [%1], 16;" :: "r"(dst_u32), "l"(src_ptr))
#define CP_COMMIT()  asm volatile("cp.async.commit_group;" ::: "memory")
#define CP_WAIT(N)   asm volatile("cp.async.wait_group %0;" :: "n"(N) : "memory")

#define LDSM_X4(r0, r1, r2, r3, addr) \
    asm volatile("ldmatrix.sync.aligned.m8n8.x4.shared.b16 {%0,%1,%2,%3}, [%4];" \
        : "=r"(r0), "=r"(r1), "=r"(r2), "=r"(r3) : "r"(addr))

#define REDG_ADD_V2(ptr, va, vb) \
    asm volatile("red.global.add.v2.f32 [%0], {%1, %2};" :: "l"(ptr), "f"(va), "f"(vb) : "memory")

__device__ __forceinline__ void mma_f16(float* c, const uint32_t* a, const uint32_t* b) {
    asm volatile(
        "mma.sync.aligned.m16n8k16.row.col.f32.f16.f16.f32 "
        "{%0,%1,%2,%3}, {%4,%5,%6,%7}, {%8,%9}, {%0,%1,%2,%3};"
        : "+f"(c[0]), "+f"(c[1]), "+f"(c[2]), "+f"(c[3])
        : "r"(a[0]), "r"(a[1]), "r"(a[2]), "r"(a[3]), "r"(b[0]), "r"(b[1]));
}

// ============================================================
// fp32 -> fp16 conversion kernels
// ============================================================
__device__ __forceinline__ uint2 cvt4(float4 v) {
    __half2 h01 = __floats2half2_rn(v.x, v.y);
    __half2 h23 = __floats2half2_rn(v.z, v.w);
    uint2 o;
    o.x = *reinterpret_cast<uint32_t*>(&h01);
    o.y = *reinterpret_cast<uint32_t*>(&h23);
    return o;
}
__global__ void conv_w13(const float4* __restrict__ src) {
    size_t i = (size_t)blockIdx.x * 256 + threadIdx.x;
    ((uint2*)g_wh13)[i] = cvt4(src[i]);
}
__global__ void conv_w2(const float4* __restrict__ src) {
    size_t i = (size_t)blockIdx.x * 256 + threadIdx.x;
    ((uint2*)g_wh2)[i] = cvt4(src[i]);
}
__global__ void conv_x(const float4* __restrict__ src) {
    size_t i = (size_t)blockIdx.x * 256 + threadIdx.x;
    ((uint2*)g_xh)[i] = cvt4(src[i]);
}

// ============================================================
// Routing: softmax -> top2 -> renormalize; padded per-expert slot lists (x128).
// ============================================================
__global__ void routing_kernel(const float* __restrict__ logits) {
    __shared__ int s_cnt[N_EXP];
    __shared__ int s_cur[N_EXP];
    __shared__ int s_off[N_EXP + 1];

    const int t = threadIdx.x;
    if (t < N_EXP) { s_cnt[t] = 0; s_cur[t] = 0; }
    for (int s = t; s < MAXSLOT; s += blockDim.x) g_token_of_slot[s] = -1;
    __syncthreads();

    int e1 = 0, e2 = 0;
    float w1 = 0.f, w2 = 0.f;
    if (t < T_TOK) {
        float l[N_EXP];
#pragma unroll
        for (int e = 0; e < N_EXP; e++) l[e] = logits[t * N_EXP + e];
        float b1 = -1e30f;
#pragma unroll
        for (int e = 0; e < N_EXP; e++) if (l[e] > b1) { b1 = l[e]; e1 = e; }
        float b2 = -1e30f;
        e2 = (e1 == 0) ? 1 : 0;
#pragma unroll
        for (int e = 0; e < N_EXP; e++) if (e != e1 && l[e] > b2) { b2 = l[e]; e2 = e; }
        float p2 = expf(b2 - b1);
        w1 = 1.f / (1.f + p2);
        w2 = p2 / (1.f + p2);
        atomicAdd(&s_cnt[e1], 1);
        atomicAdd(&s_cnt[e2], 1);
    }
    __syncthreads();

    if (t == 0) {
        int off = 0;
        for (int e = 0; e < N_EXP; e++) {
            s_off[e] = off;
            int tiles = (s_cnt[e] + BM - 1) / BM;
            for (int i = 0; i < tiles; i++) g_tile_expert[off / BM + i] = e;
            off += tiles * BM;
        }
        s_off[N_EXP] = off;
        g_num_tiles = off / BM;
    }
    __syncthreads();

    if (t < T_TOK) {
        int p = atomicAdd(&s_cur[e1], 1);
        int s = s_off[e1] + p;
        g_token_of_slot[s] = t;
        g_slot_weight[s]   = w1;
        p = atomicAdd(&s_cur[e2], 1);
        s = s_off[e2] + p;
        g_token_of_slot[s] = t;
        g_slot_weight[s]   = w2;
    }
}

// ============================================================
// Fragments via ldmatrix.x4. 16 warps: wm=wid&3 (32 rows), wn=wid>>2 (32 cols).
// Chunk k64 = 4 k16 steps; kbyte = ks*32.
// ============================================================
struct FragAddr {
    uint32_t a[2];   // [mf] stage-0 addr at ks=0
    uint32_t b[2];   // [np]
};

__device__ __forceinline__ FragAddr make_frag_addrs(uint32_t smBase, int wid, int lid) {
    FragAddr fa;
    const int wm = wid & 3, wn = wid >> 2;
#pragma unroll
    for (int mf = 0; mf < 2; mf++) {
        const int row = wm * 32 + mf * 16 + (lid & 15);
        fa.a[mf] = smBase + row * ROW_B + (lid >> 4) * 16;
    }
#pragma unroll
    for (int np = 0; np < 2; np++) {
        const int n = wn * 32 + np * 16 + ((lid >> 4) * 8) + (lid & 7);
        fa.b[np] = smBase + A_HALVES * 2 + n * ROW_B + ((lid >> 3) & 1) * 16;
    }
    return fa;
}

__device__ __forceinline__ void mma_chunk(const FragAddr& fa, uint32_t stOff,
                                          float acc[2][4][4]) {
#pragma unroll
    for (int ks = 0; ks < 4; ks++) {
        const uint32_t kb = stOff + ks * 32;
        uint32_t af[2][4];
#pragma unroll
        for (int mf = 0; mf < 2; mf++)
            LDSM_X4(af[mf][0], af[mf][1], af[mf][2], af[mf][3], fa.a[mf] + kb);
        uint32_t bf[4][2];
#pragma unroll
        for (int np = 0; np < 2; np++)
            LDSM_X4(bf[2 * np][0], bf[2 * np][1], bf[2 * np + 1][0], bf[2 * np + 1][1],
                    fa.b[np] + kb);
#pragma unroll
        for (int mf = 0; mf < 2; mf++)
#pragma unroll
            for (int nf = 0; nf < 4; nf++)
                mma_f16(acc[mf][nf], af[mf], bf[nf]);
    }
}

// loaders: each thread 2 A segs + 2 B segs of 16B (segs sb, sb+4 of 8 per 128B row)
__device__ __forceinline__ void issue_chunk(uint32_t aDst, uint32_t bDst,
                                            const __half* aSrc, const __half* bSrc,
                                            int kOff, int sb) {
    CP_ASYNC16(aDst,      aSrc + kOff + sb * 8);
    CP_ASYNC16(aDst + 64, aSrc + kOff + sb * 8 + 32);
    CP_ASYNC16(bDst,      bSrc + kOff + sb * 8);
    CP_ASYNC16(bDst + 64, bSrc + kOff + sb * 8 + 32);
    CP_COMMIT();
}

// ============================================================
// GEMM1 + SiLU*up. B rows interleaved gate/up. grid = (MAXTILES, I/64)
// ============================================================
__global__ __launch_bounds__(NTHREADS, 2)
void gemm1_mma(void) {
    const int tile_m = blockIdx.x;
    if (tile_m >= g_num_tiles) return;
    const int e   = g_tile_expert[tile_m];
    const int nbJ = blockIdx.y * 64;

    extern __shared__ __half smh[];

    const int tid = threadIdx.x;
    const int wid = tid >> 5, lid = tid & 31;
    const int fg = lid >> 2, ftg = lid & 3;
    const int fwm = wid & 3, fwn = wid >> 2;

    const int r  = tid >> 2;            // 0..127
    const int sb = tid & 3;             // seg 0..3 (pairs with sb+4)
    const int tokr = g_token_of_slot[tile_m * BM + r];
    const __half* aSrc = g_xh + (size_t)(tokr < 0 ? 0 : tokr) * H_DIM;
    const int j = r >> 1;
    const int wrow = (r & 1) ? (I_DIM + nbJ + j) : (nbJ + j);
    const __half* bSrc = g_wh13 + ((size_t)e * 2 * I_DIM + wrow) * H_DIM;

    const uint32_t smBase = smem_u32(smh);
    const FragAddr fa = make_frag_addrs(smBase, wid, lid);
    uint32_t aDst[NSTAGE], bDst[NSTAGE];
#pragma unroll
    for (int s = 0; s < NSTAGE; s++) {
        aDst[s] = smBase + s * STAGE_BYTES + r * ROW_B + sb * 16;
        bDst[s] = aDst[s] + A_HALVES * 2;
    }

    float acc[2][4][4];
#pragma unroll
    for (int a = 0; a < 2; a++)
#pragma unroll
        for (int b = 0; b < 4; b++)
#pragma unroll
            for (int c = 0; c < 4; c++) acc[a][b][c] = 0.f;

    const int NC = H_DIM / BK;   // 32
    issue_chunk(aDst[0], bDst[0], aSrc, bSrc, 0 * BK, sb);
    issue_chunk(aDst[1], bDst[1], aSrc, bSrc, 1 * BK, sb);

    int stage = 0, stage2 = 2;
#pragma unroll 1
    for (int c = 0; c < NC; c++) {
        if (c + 1 < NC) CP_WAIT(1); else CP_WAIT(0);
        __syncthreads();
        if (c + 2 < NC)
            issue_chunk(aDst[stage2], bDst[stage2], aSrc, bSrc, (c + 2) * BK, sb);
        mma_chunk(fa, (uint32_t)(stage * STAGE_BYTES), acc);
        stage = (stage + 1 == NSTAGE) ? 0 : stage + 1;
        stage2 = (stage2 + 1 == NSTAGE) ? 0 : stage2 + 1;
    }

    // epilogue: silu(gate)*up; c-pair (even,odd) = (gate, up) of same col; store fp16
#pragma unroll
    for (int mf = 0; mf < 2; mf++) {
#pragma unroll
        for (int half = 0; half < 2; half++) {
            const int slot = tile_m * BM + fwm * 32 + mf * 16 + fg + half * 8;
            if (g_token_of_slot[slot] >= 0) {
                __half* dst = g_act + (size_t)slot * I_DIM + nbJ;
#pragma unroll
                for (int nf = 0; nf < 4; nf++) {
                    const int jj = fwn * 16 + nf * 4 + ftg;
                    const float gt = acc[mf][nf][half * 2 + 0];
                    const float up = acc[mf][nf][half * 2 + 1];
                    dst[jj] = __float2half_rn(up * gt / (1.f + expf(-gt)));
                }
            }
        }
    }
}

// ============================================================
// GEMM2 + weighted scatter via red.global.v2.f32. grid = (MAXTILES, H/128)
// ============================================================
__global__ __launch_bounds__(NTHREADS, 2)
void gemm2_mma(float* __restrict__ out) {
    const int tile_m = blockIdx.x;
    if (tile_m >= g_num_tiles) return;
    const int e     = g_tile_expert[tile_m];
    const int nbase = blockIdx.y * BN;

    extern __shared__ __half smh[];

    const int tid = threadIdx.x;
    const int wid = tid >> 5, lid = tid & 31;
    const int fg = lid >> 2, ftg = lid & 3;
    const int fwm = wid & 3, fwn = wid >> 2;

    const int r  = tid >> 2;
    const int sb = tid & 3;
    const __half* aSrc = g_act + (size_t)(tile_m * BM + r) * I_DIM;  // pad rows: garbage, rows discarded
    const __half* bSrc = g_wh2 + ((size_t)e * H_DIM + (nbase + r)) * I_DIM;

    const uint32_t smBase = smem_u32(smh);
    const FragAddr fa = make_frag_addrs(smBase, wid, lid);
    uint32_t aDst[NSTAGE], bDst[NSTAGE];
#pragma unroll
    for (int s = 0; s < NSTAGE; s++) {
        aDst[s] = smBase + s * STAGE_BYTES + r * ROW_B + sb * 16;
        bDst[s] = aDst[s] + A_HALVES * 2;
    }

    float acc[2][4][4];
#pragma unroll
    for (int a = 0; a < 2; a++)
#pragma unroll
        for (int b = 0; b < 4; b++)
#pragma unroll
            for (int c = 0; c < 4; c++) acc[a][b][c] = 0.f;

    const int NC = I_DIM / BK;   // 22
    issue_chunk(aDst[0], bDst[0], aSrc, bSrc, 0 * BK, sb);
    issue_chunk(aDst[1], bDst[1], aSrc, bSrc, 1 * BK, sb);

    int stage = 0, stage2 = 2;
#pragma unroll 1
    for (int c = 0; c < NC; c++) {
        if (c + 1 < NC) CP_WAIT(1); else CP_WAIT(0);
        __syncthreads();
        if (c + 2 < NC)
            issue_chunk(aDst[stage2], bDst[stage2], aSrc, bSrc, (c + 2) * BK, sb);
        mma_chunk(fa, (uint32_t)(stage * STAGE_BYTES), acc);
        stage = (stage + 1 == NSTAGE) ? 0 : stage + 1;
        stage2 = (stage2 + 1 == NSTAGE) ? 0 : stage2 + 1;
    }

#pragma unroll
    for (int mf = 0; mf < 2; mf++) {
#pragma unroll
        for (int half = 0; half < 2; half++) {
            const int slot = tile_m * BM + fwm * 32 + mf * 16 + fg + half * 8;
            const int tok  = g_token_of_slot[slot];
            if (tok >= 0) {
                const float w = g_slot_weight[slot];
                float* dst = out + (size_t)tok * H_DIM + nbase;
#pragma unroll
                for (int nf = 0; nf < 4; nf++) {
                    const int col = fwn * 32 + nf * 8 + ftg * 2;   // even -> 8B aligned
                    REDG_ADD_V2(dst + col,
                                w * acc[mf][nf][half * 2 + 0],
                                w * acc[mf][nf][half * 2 + 1]);
                }
            }
        }
    }
}

// ============================================================
extern "C" void kernel_launch(void* const* d_in, const int* in_sizes, int n_in,
                              void* d_out, int out_size) {
    const float* x      = (const float*)d_in[0];   // [1024, 2048]
    const float* logits = (const float*)d_in[1];   // [1024, 8]
    const float* w13    = (const float*)d_in[2];   // [8, 2816, 2048]
    const float* w2     = (const float*)d_in[3];   // [8, 2048, 1408]
    float* out = (float*)d_out;                    // [1024, 2048]
    (void)in_sizes; (void)n_in;

    cudaFuncSetAttribute(gemm1_mma, cudaFuncAttributeMaxDynamicSharedMemorySize, SMEM_DYN_BYTES);
    cudaFuncSetAttribute(gemm2_mma, cudaFuncAttributeMaxDynamicSharedMemorySize, SMEM_DYN_BYTES);

    cudaMemsetAsync(d_out, 0, (size_t)out_size * sizeof(float));
    conv_x  <<<(T_TOK * H_DIM) / 1024, 256>>>((const float4*)x);
    conv_w13<<<(N_EXP * 2 * I_DIM * H_DIM) / 1024, 256>>>((const float4*)w13);
    conv_w2 <<<(N_EXP * H_DIM * I_DIM) / 1024, 256>>>((const float4*)w2);
    routing_kernel<<<1, 1024>>>(logits);
    gemm1_mma<<<dim3(MAXTILES, I_DIM / 64), NTHREADS, SMEM_DYN_BYTES>>>();
    gemm2_mma<<<dim3(MAXTILES, H_DIM / BN), NTHREADS, SMEM_DYN_BYTES>>>(out);
}

// round 14
// speedup vs baseline: 2.1314x; 1.0740x over previous
#include <cuda_runtime.h>
#include <cuda_fp16.h>
#include <cstdint>
#include <math.h>

// ---------------- problem constants ----------------
#define T_TOK 1024
#define H_DIM 2048
#define I_DIM 1408
#define N_EXP 8

// ---------------- tiling ----------------
#define BM 128
#define BN 128
#define BK 64            // halves per chunk row (128 B)
#define NSTAGE 3
#define MAXSLOT  3072
#define MAXTILES 24
#define NTHREADS 512

#define NB1Y (I_DIM / 64)        // 22 gemm1 n-tiles
#define CONV_ROWS 22             // extra grid rows carrying conv_w2 blocks
#define W2_F4      5767168       // 8*2048*1408/4
#define W2_SLICES  512
#define W2_PER_BLK (W2_F4 / W2_SLICES)   // 11264 float4 per conv block

#define ROW_H 72                                  // halves per smem row (144 B, LDSM conflict-free)
#define ROW_B (ROW_H * 2)
#define A_HALVES (BM * ROW_H)                     // 18 KB
#define STAGE_HALVES (2 * A_HALVES)               // A+B = 36 KB
#define STAGE_BYTES (STAGE_HALVES * 2)
#define SMEM_DYN_BYTES (NSTAGE * STAGE_BYTES)     // 108 KB -> 2 blocks/SM

// ---------------- scratch (static; ~151 MB total) ----------------
__device__ int    g_token_of_slot[MAXSLOT];
__device__ float  g_slot_weight[MAXSLOT];
__device__ int    g_tile_expert[MAXTILES];
__device__ int    g_num_tiles;
__device__ __half g_act[(size_t)MAXSLOT * I_DIM];                 // 8.7 MB
__device__ __half g_xh[(size_t)T_TOK * H_DIM];                    // 4 MB
__device__ __half g_wh13[(size_t)N_EXP * 2 * I_DIM * H_DIM];      // 92.3 MB
__device__ __half g_wh2[(size_t)N_EXP * H_DIM * I_DIM];           // 46.2 MB

// ---------------- PTX helpers (baseline sm_80/90; nothing 'a'-gated) ----------------
__device__ __forceinline__ uint32_t smem_u32(const void* p) {
    uint32_t a;
    asm("{ .reg .u64 t; cvta.to.shared.u64 t, %1; cvt.u32.u64 %0, t; }" : "=r"(a) : "l"(p));
    return a;
}
#define CP_ASYNC16(dst_u32, src_ptr) \
    asm volatile("cp.async.cg.shared.global [%0], [%1], 16;" :: "r"(dst_u32), "l"(src_ptr))
#define CP_COMMIT()  asm volatile("cp.async.commit_group;" ::: "memory")
#define CP_WAIT(N)   asm volatile("cp.async.wait_group %0;" :: "n"(N) : "memory")

#define LDSM_X4(r0, r1, r2, r3, addr) \
    asm volatile("ldmatrix.sync.aligned.m8n8.x4.shared.b16 {%0,%1,%2,%3}, [%4];" \
        : "=r"(r0), "=r"(r1), "=r"(r2), "=r"(r3) : "r"(addr))

#define REDG_ADD_V2(ptr, va, vb) \
    asm volatile("red.global.add.v2.f32 [%0], {%1, %2};" :: "l"(ptr), "f"(va), "f"(vb) : "memory")

__device__ __forceinline__ void mma_f16(float* c, const uint32_t* a, const uint32_t* b) {
    asm volatile(
        "mma.sync.aligned.m16n8k16.row.col.f32.f16.f16.f32 "
        "{%0,%1,%2,%3}, {%4,%5,%6,%7}, {%8,%9}, {%0,%1,%2,%3};"
        : "+f"(c[0]), "+f"(c[1]), "+f"(c[2]), "+f"(c[3])
        : "r"(a[0]), "r"(a[1]), "r"(a[2]), "r"(a[3]), "r"(b[0]), "r"(b[1]));
}

// ============================================================
// fp32 -> fp16 conversion helpers / kernels
// ============================================================
__device__ __forceinline__ uint2 cvt4(float4 v) {
    __half2 h01 = __floats2half2_rn(v.x, v.y);
    __half2 h23 = __floats2half2_rn(v.z, v.w);
    uint2 o;
    o.x = *reinterpret_cast<uint32_t*>(&h01);
    o.y = *reinterpret_cast<uint32_t*>(&h23);
    return o;
}
__global__ void conv_w13(const float4* __restrict__ src) {
    size_t i = (size_t)blockIdx.x * 256 + threadIdx.x;
    ((uint2*)g_wh13)[i] = cvt4(src[i]);
}
__global__ void conv_x(const float4* __restrict__ src) {
    size_t i = (size_t)blockIdx.x * 256 + threadIdx.x;
    ((uint2*)g_xh)[i] = cvt4(src[i]);
}

// ============================================================
// Routing: softmax -> top2 -> renormalize; padded per-expert slot lists (x128).
// ============================================================
__global__ void routing_kernel(const float* __restrict__ logits) {
    __shared__ int s_cnt[N_EXP];
    __shared__ int s_cur[N_EXP];
    __shared__ int s_off[N_EXP + 1];

    const int t = threadIdx.x;
    if (t < N_EXP) { s_cnt[t] = 0; s_cur[t] = 0; }
    for (int s = t; s < MAXSLOT; s += blockDim.x) g_token_of_slot[s] = -1;
    __syncthreads();

    int e1 = 0, e2 = 0;
    float w1 = 0.f, w2 = 0.f;
    if (t < T_TOK) {
        float l[N_EXP];
#pragma unroll
        for (int e = 0; e < N_EXP; e++) l[e] = logits[t * N_EXP + e];
        float b1 = -1e30f;
#pragma unroll
        for (int e = 0; e < N_EXP; e++) if (l[e] > b1) { b1 = l[e]; e1 = e; }
        float b2 = -1e30f;
        e2 = (e1 == 0) ? 1 : 0;
#pragma unroll
        for (int e = 0; e < N_EXP; e++) if (e != e1 && l[e] > b2) { b2 = l[e]; e2 = e; }
        float p2 = expf(b2 - b1);
        w1 = 1.f / (1.f + p2);
        w2 = p2 / (1.f + p2);
        atomicAdd(&s_cnt[e1], 1);
        atomicAdd(&s_cnt[e2], 1);
    }
    __syncthreads();

    if (t == 0) {
        int off = 0;
        for (int e = 0; e < N_EXP; e++) {
            s_off[e] = off;
            int tiles = (s_cnt[e] + BM - 1) / BM;
            for (int i = 0; i < tiles; i++) g_tile_expert[off / BM + i] = e;
            off += tiles * BM;
        }
        s_off[N_EXP] = off;
        g_num_tiles = off / BM;
    }
    __syncthreads();

    if (t < T_TOK) {
        int p = atomicAdd(&s_cur[e1], 1);
        int s = s_off[e1] + p;
        g_token_of_slot[s] = t;
        g_slot_weight[s]   = w1;
        p = atomicAdd(&s_cur[e2], 1);
        s = s_off[e2] + p;
        g_token_of_slot[s] = t;
        g_slot_weight[s]   = w2;
    }
}

// ============================================================
// Fragments via ldmatrix.x4. 16 warps: wm=wid&3 (32 rows), wn=wid>>2 (32 cols).
// Chunk k64 = 4 k16 steps.
// ============================================================
struct FragAddr {
    uint32_t a[2];
    uint32_t b[2];
};

__device__ __forceinline__ FragAddr make_frag_addrs(uint32_t smBase, int wid, int lid) {
    FragAddr fa;
    const int wm = wid & 3, wn = wid >> 2;
#pragma unroll
    for (int mf = 0; mf < 2; mf++) {
        const int row = wm * 32 + mf * 16 + (lid & 15);
        fa.a[mf] = smBase + row * ROW_B + (lid >> 4) * 16;
    }
#pragma unroll
    for (int np = 0; np < 2; np++) {
        const int n = wn * 32 + np * 16 + ((lid >> 4) * 8) + (lid & 7);
        fa.b[np] = smBase + A_HALVES * 2 + n * ROW_B + ((lid >> 3) & 1) * 16;
    }
    return fa;
}

__device__ __forceinline__ void mma_chunk(const FragAddr& fa, uint32_t stOff,
                                          float acc[2][4][4]) {
#pragma unroll
    for (int ks = 0; ks < 4; ks++) {
        const uint32_t kb = stOff + ks * 32;
        uint32_t af[2][4];
#pragma unroll
        for (int mf = 0; mf < 2; mf++)
            LDSM_X4(af[mf][0], af[mf][1], af[mf][2], af[mf][3], fa.a[mf] + kb);
        uint32_t bf[4][2];
#pragma unroll
        for (int np = 0; np < 2; np++)
            LDSM_X4(bf[2 * np][0], bf[2 * np][1], bf[2 * np + 1][0], bf[2 * np + 1][1],
                    fa.b[np] + kb);
#pragma unroll
        for (int mf = 0; mf < 2; mf++)
#pragma unroll
            for (int nf = 0; nf < 4; nf++)
                mma_f16(acc[mf][nf], af[mf], bf[nf]);
    }
}

__device__ __forceinline__ void issue_chunk(uint32_t aDst, uint32_t bDst,
                                            const __half* aSrc, const __half* bSrc,
                                            int kOff, int sb) {
    CP_ASYNC16(aDst,      aSrc + kOff + sb * 8);
    CP_ASYNC16(aDst + 64, aSrc + kOff + sb * 8 + 32);
    CP_ASYNC16(bDst,      bSrc + kOff + sb * 8);
    CP_ASYNC16(bDst + 64, bSrc + kOff + sb * 8 + 32);
    CP_COMMIT();
}

// ============================================================
// GEMM1 + SiLU*up, with conv_w2 fused as filler blocks (blockIdx.y >= NB1Y).
// grid = (MAXTILES, NB1Y + CONV_ROWS)
// ============================================================
__global__ __launch_bounds__(NTHREADS, 2)
void gemm1_mma(const float4* __restrict__ w2src) {
    // ---- conv_w2 filler blocks: disjoint from gemm1's data; gemm2 (next
    // kernel) is the only consumer of g_wh2, so no intra-kernel ordering needed.
    if (blockIdx.y >= NB1Y) {
        const int c = (blockIdx.y - NB1Y) * gridDim.x + blockIdx.x;
        if (c < W2_SLICES) {
            const float4* src = w2src + (size_t)c * W2_PER_BLK;
            uint2* dst = ((uint2*)g_wh2) + (size_t)c * W2_PER_BLK;
#pragma unroll 2
            for (int i = threadIdx.x; i < W2_PER_BLK; i += NTHREADS)
                dst[i] = cvt4(src[i]);
        }
        return;
    }

    const int tile_m = blockIdx.x;
    if (tile_m >= g_num_tiles) return;
    const int e   = g_tile_expert[tile_m];
    const int nbJ = blockIdx.y * 64;

    extern __shared__ __half smh[];

    const int tid = threadIdx.x;
    const int wid = tid >> 5, lid = tid & 31;
    const int fg = lid >> 2, ftg = lid & 3;
    const int fwm = wid & 3, fwn = wid >> 2;

    const int r  = tid >> 2;            // 0..127
    const int sb = tid & 3;             // seg 0..3 (pairs with sb+4)
    const int tokr = g_token_of_slot[tile_m * BM + r];
    const __half* aSrc = g_xh + (size_t)(tokr < 0 ? 0 : tokr) * H_DIM;
    const int j = r >> 1;
    const int wrow = (r & 1) ? (I_DIM + nbJ + j) : (nbJ + j);
    const __half* bSrc = g_wh13 + ((size_t)e * 2 * I_DIM + wrow) * H_DIM;

    const uint32_t smBase = smem_u32(smh);
    const FragAddr fa = make_frag_addrs(smBase, wid, lid);
    uint32_t aDst[NSTAGE], bDst[NSTAGE];
#pragma unroll
    for (int s = 0; s < NSTAGE; s++) {
        aDst[s] = smBase + s * STAGE_BYTES + r * ROW_B + sb * 16;
        bDst[s] = aDst[s] + A_HALVES * 2;
    }

    float acc[2][4][4];
#pragma unroll
    for (int a = 0; a < 2; a++)
#pragma unroll
        for (int b = 0; b < 4; b++)
#pragma unroll
            for (int c = 0; c < 4; c++) acc[a][b][c] = 0.f;

    const int NC = H_DIM / BK;   // 32
    issue_chunk(aDst[0], bDst[0], aSrc, bSrc, 0 * BK, sb);
    issue_chunk(aDst[1], bDst[1], aSrc, bSrc, 1 * BK, sb);

    int stage = 0, stage2 = 2;
#pragma unroll 1
    for (int c = 0; c < NC; c++) {
        if (c + 1 < NC) CP_WAIT(1); else CP_WAIT(0);
        __syncthreads();
        if (c + 2 < NC)
            issue_chunk(aDst[stage2], bDst[stage2], aSrc, bSrc, (c + 2) * BK, sb);
        mma_chunk(fa, (uint32_t)(stage * STAGE_BYTES), acc);
        stage = (stage + 1 == NSTAGE) ? 0 : stage + 1;
        stage2 = (stage2 + 1 == NSTAGE) ? 0 : stage2 + 1;
    }

    // epilogue: silu(gate)*up; c-pair (even,odd) = (gate, up) of same col; store fp16
#pragma unroll
    for (int mf = 0; mf < 2; mf++) {
#pragma unroll
        for (int half = 0; half < 2; half++) {
            const int slot = tile_m * BM + fwm * 32 + mf * 16 + fg + half * 8;
            if (g_token_of_slot[slot] >= 0) {
                __half* dst = g_act + (size_t)slot * I_DIM + nbJ;
#pragma unroll
                for (int nf = 0; nf < 4; nf++) {
                    const int jj = fwn * 16 + nf * 4 + ftg;
                    const float gt = acc[mf][nf][half * 2 + 0];
                    const float up = acc[mf][nf][half * 2 + 1];
                    dst[jj] = __float2half_rn(up * gt / (1.f + expf(-gt)));
                }
            }
        }
    }
}

// ============================================================
// GEMM2 + weighted scatter via red.global.v2.f32. grid = (MAXTILES, H/128)
// ============================================================
__global__ __launch_bounds__(NTHREADS, 2)
void gemm2_mma(float* __restrict__ out) {
    const int tile_m = blockIdx.x;
    if (tile_m >= g_num_tiles) return;
    const int e     = g_tile_expert[tile_m];
    const int nbase = blockIdx.y * BN;

    extern __shared__ __half smh[];

    const int tid = threadIdx.x;
    const int wid = tid >> 5, lid = tid & 31;
    const int fg = lid >> 2, ftg = lid & 3;
    const int fwm = wid & 3, fwn = wid >> 2;

    const int r  = tid >> 2;
    const int sb = tid & 3;
    const __half* aSrc = g_act + (size_t)(tile_m * BM + r) * I_DIM;  // pad rows: garbage, rows discarded
    const __half* bSrc = g_wh2 + ((size_t)e * H_DIM + (nbase + r)) * I_DIM;

    const uint32_t smBase = smem_u32(smh);
    const FragAddr fa = make_frag_addrs(smBase, wid, lid);
    uint32_t aDst[NSTAGE], bDst[NSTAGE];
#pragma unroll
    for (int s = 0; s < NSTAGE; s++) {
        aDst[s] = smBase + s * STAGE_BYTES + r * ROW_B + sb * 16;
        bDst[s] = aDst[s] + A_HALVES * 2;
    }

    float acc[2][4][4];
#pragma unroll
    for (int a = 0; a < 2; a++)
#pragma unroll
        for (int b = 0; b < 4; b++)
#pragma unroll
            for (int c = 0; c < 4; c++) acc[a][b][c] = 0.f;

    const int NC = I_DIM / BK;   // 22
    issue_chunk(aDst[0], bDst[0], aSrc, bSrc, 0 * BK, sb);
    issue_chunk(aDst[1], bDst[1], aSrc, bSrc, 1 * BK, sb);

    int stage = 0, stage2 = 2;
#pragma unroll 1
    for (int c = 0; c < NC; c++) {
        if (c + 1 < NC) CP_WAIT(1); else CP_WAIT(0);
        __syncthreads();
        if (c + 2 < NC)
            issue_chunk(aDst[stage2], bDst[stage2], aSrc, bSrc, (c + 2) * BK, sb);
        mma_chunk(fa, (uint32_t)(stage * STAGE_BYTES), acc);
        stage = (stage + 1 == NSTAGE) ? 0 : stage + 1;
        stage2 = (stage2 + 1 == NSTAGE) ? 0 : stage2 + 1;
    }

#pragma unroll
    for (int mf = 0; mf < 2; mf++) {
#pragma unroll
        for (int half = 0; half < 2; half++) {
            const int slot = tile_m * BM + fwm * 32 + mf * 16 + fg + half * 8;
            const int tok  = g_token_of_slot[slot];
            if (tok >= 0) {
                const float w = g_slot_weight[slot];
                float* dst = out + (size_t)tok * H_DIM + nbase;
#pragma unroll
                for (int nf = 0; nf < 4; nf++) {
                    const int col = fwn * 32 + nf * 8 + ftg * 2;   // even -> 8B aligned
                    REDG_ADD_V2(dst + col,
                                w * acc[mf][nf][half * 2 + 0],
                                w * acc[mf][nf][half * 2 + 1]);
                }
            }
        }
    }
}

// ============================================================
extern "C" void kernel_launch(void* const* d_in, const int* in_sizes, int n_in,
                              void* d_out, int out_size) {
    const float* x      = (const float*)d_in[0];   // [1024, 2048]
    const float* logits = (const float*)d_in[1];   // [1024, 8]
    const float* w13    = (const float*)d_in[2];   // [8, 2816, 2048]
    const float* w2     = (const float*)d_in[3];   // [8, 2048, 1408]
    float* out = (float*)d_out;                    // [1024, 2048]
    (void)in_sizes; (void)n_in;

    cudaFuncSetAttribute(gemm1_mma, cudaFuncAttributeMaxDynamicSharedMemorySize, SMEM_DYN_BYTES);
    cudaFuncSetAttribute(gemm2_mma, cudaFuncAttributeMaxDynamicSharedMemorySize, SMEM_DYN_BYTES);

    cudaMemsetAsync(d_out, 0, (size_t)out_size * sizeof(float));
    conv_x  <<<(T_TOK * H_DIM) / 1024, 256>>>((const float4*)x);
    conv_w13<<<(N_EXP * 2 * I_DIM * H_DIM) / 1024, 256>>>((const float4*)w13);
    routing_kernel<<<1, 1024>>>(logits);
    // gemm1 grid carries 512 conv_w2 filler blocks (blockIdx.y >= NB1Y)
    gemm1_mma<<<dim3(MAXTILES, NB1Y + CONV_ROWS), NTHREADS, SMEM_DYN_BYTES>>>((const float4*)w2);
    gemm2_mma<<<dim3(MAXTILES, H_DIM / BN), NTHREADS, SMEM_DYN_BYTES>>>(out);
}

// round 15
// speedup vs baseline: 2.2785x; 1.0690x over previous
#include <cuda_runtime.h>
#include <cuda_fp16.h>
#include <cstdint>
#include <math.h>

// ---------------- problem constants ----------------
#define T_TOK 1024
#define H_DIM 2048
#define I_DIM 1408
#define N_EXP 8

// ---------------- tiling ----------------
#define BM 128
#define BN 128
#define BK 64            // halves per chunk row (128 B)
#define NSTAGE 3
#define MAXSLOT  3072
#define MAXTILES 24
#define NTHREADS 512

#define NB1Y (I_DIM / 64)        // 22 gemm1 n-tiles
#define CONV_ROWS 22             // extra grid rows carrying conv_w2 blocks
#define W2_F4      5767168       // 8*2048*1408/4
#define W2_SLICES  512
#define W2_PER_BLK (W2_F4 / W2_SLICES)   // 11264 float4 per conv block

// prep kernel layout: block 0 = routing; 1..X_BLKS = conv_x; rest = conv_w13
#define X_F4       524288        // 1024*2048/4
#define X_BLKS     512           // 256 thr x 4 f4
#define W13_F4     11534336      // 8*2816*2048/4
#define W13_BLKS   11264         // 256 thr x 4 f4
#define PREP_BLKS  (1 + X_BLKS + W13_BLKS)

#define ROW_H 72                                  // halves per smem row (144 B, LDSM conflict-free)
#define ROW_B (ROW_H * 2)
#define A_HALVES (BM * ROW_H)                     // 18 KB
#define STAGE_HALVES (2 * A_HALVES)               // A+B = 36 KB
#define STAGE_BYTES (STAGE_HALVES * 2)
#define SMEM_DYN_BYTES (NSTAGE * STAGE_BYTES)     // 108 KB -> 2 blocks/SM

// ---------------- scratch (static; ~151 MB total) ----------------
__device__ int    g_token_of_slot[MAXSLOT];
__device__ float  g_slot_weight[MAXSLOT];
__device__ int    g_tile_expert[MAXTILES];
__device__ int    g_num_tiles;
__device__ __half g_act[(size_t)MAXSLOT * I_DIM];                 // 8.7 MB
__device__ __half g_xh[(size_t)T_TOK * H_DIM];                    // 4 MB
__device__ __half g_wh13[(size_t)N_EXP * 2 * I_DIM * H_DIM];      // 92.3 MB
__device__ __half g_wh2[(size_t)N_EXP * H_DIM * I_DIM];           // 46.2 MB

// ---------------- PTX helpers (baseline sm_80/90; nothing 'a'-gated) ----------------
__device__ __forceinline__ uint32_t smem_u32(const void* p) {
    uint32_t a;
    asm("{ .reg .u64 t; cvta.to.shared.u64 t, %1; cvt.u32.u64 %0, t; }" : "=r"(a) : "l"(p));
    return a;
}
#define CP_ASYNC16(dst_u32, src_ptr) \
    asm volatile("cp.async.cg.shared.global [%0], [%1], 16;" :: "r"(dst_u32), "l"(src_ptr))
#define CP_COMMIT()  asm volatile("cp.async.commit_group;" ::: "memory")
#define CP_WAIT(N)   asm volatile("cp.async.wait_group %0;" :: "n"(N) : "memory")

#define LDSM_X4(r0, r1, r2, r3, addr) \
    asm volatile("ldmatrix.sync.aligned.m8n8.x4.shared.b16 {%0,%1,%2,%3}, [%4];" \
        : "=r"(r0), "=r"(r1), "=r"(r2), "=r"(r3) : "r"(addr))

#define REDG_ADD_V2(ptr, va, vb) \
    asm volatile("red.global.add.v2.f32 [%0], {%1, %2};" :: "l"(ptr), "f"(va), "f"(vb) : "memory")

__device__ __forceinline__ void mma_f16(float* c, const uint32_t* a, const uint32_t* b) {
    asm volatile(
        "mma.sync.aligned.m16n8k16.row.col.f32.f16.f16.f32 "
        "{%0,%1,%2,%3}, {%4,%5,%6,%7}, {%8,%9}, {%0,%1,%2,%3};"
        : "+f"(c[0]), "+f"(c[1]), "+f"(c[2]), "+f"(c[3])
        : "r"(a[0]), "r"(a[1]), "r"(a[2]), "r"(a[3]), "r"(b[0]), "r"(b[1]));
}

// ============================================================
// fp32 -> fp16 helpers
// ============================================================
__device__ __forceinline__ uint2 cvt4(float4 v) {
    __half2 h01 = __floats2half2_rn(v.x, v.y);
    __half2 h23 = __floats2half2_rn(v.z, v.w);
    uint2 o;
    o.x = *reinterpret_cast<uint32_t*>(&h01);
    o.y = *reinterpret_cast<uint32_t*>(&h23);
    return o;
}

// convert 1024 float4 per block (256 thr x 4, stride-256 coalesced, MLP=4)
__device__ __forceinline__ void conv_block_1024(const float4* __restrict__ src,
                                                uint2* __restrict__ dst, int tid) {
    float4 v0 = src[tid];
    float4 v1 = src[tid + 256];
    float4 v2 = src[tid + 512];
    float4 v3 = src[tid + 768];
    dst[tid]       = cvt4(v0);
    dst[tid + 256] = cvt4(v1);
    dst[tid + 512] = cvt4(v2);
    dst[tid + 768] = cvt4(v3);
}

// ============================================================
// prep: block 0 routing | blocks 1..X_BLKS conv_x | rest conv_w13. 256 thr.
// ============================================================
__global__ __launch_bounds__(256)
void prep_kernel(const float* __restrict__ logits,
                 const float4* __restrict__ x,
                 const float4* __restrict__ w13) {
    const int bid = blockIdx.x;
    const int tid = threadIdx.x;

    if (bid == 0) {
        // ---- routing: 256 threads, each handles 4 tokens ----
        __shared__ int s_cnt[N_EXP];
        __shared__ int s_cur[N_EXP];
        __shared__ int s_off[N_EXP + 1];

        if (tid < N_EXP) { s_cnt[tid] = 0; s_cur[tid] = 0; }
        for (int s = tid; s < MAXSLOT; s += 256) g_token_of_slot[s] = -1;
        __syncthreads();

        int e1v[4], e2v[4];
        float w1v[4], w2v[4];
#pragma unroll
        for (int q = 0; q < 4; q++) {
            const int t = tid + q * 256;
            float l[N_EXP];
#pragma unroll
            for (int e = 0; e < N_EXP; e++) l[e] = logits[t * N_EXP + e];
            int e1 = 0;
            float b1 = -1e30f;
#pragma unroll
            for (int e = 0; e < N_EXP; e++) if (l[e] > b1) { b1 = l[e]; e1 = e; }
            int e2 = (e1 == 0) ? 1 : 0;
            float b2 = -1e30f;
#pragma unroll
            for (int e = 0; e < N_EXP; e++) if (e != e1 && l[e] > b2) { b2 = l[e]; e2 = e; }
            float p2 = expf(b2 - b1);
            e1v[q] = e1; e2v[q] = e2;
            w1v[q] = 1.f / (1.f + p2);
            w2v[q] = p2 / (1.f + p2);
            atomicAdd(&s_cnt[e1], 1);
            atomicAdd(&s_cnt[e2], 1);
        }
        __syncthreads();

        if (tid == 0) {
            int off = 0;
            for (int e = 0; e < N_EXP; e++) {
                s_off[e] = off;
                int tiles = (s_cnt[e] + BM - 1) / BM;
                for (int i = 0; i < tiles; i++) g_tile_expert[off / BM + i] = e;
                off += tiles * BM;
            }
            s_off[N_EXP] = off;
            g_num_tiles = off / BM;
        }
        __syncthreads();

#pragma unroll
        for (int q = 0; q < 4; q++) {
            const int t = tid + q * 256;
            int p = atomicAdd(&s_cur[e1v[q]], 1);
            int s = s_off[e1v[q]] + p;
            g_token_of_slot[s] = t;
            g_slot_weight[s]   = w1v[q];
            p = atomicAdd(&s_cur[e2v[q]], 1);
            s = s_off[e2v[q]] + p;
            g_token_of_slot[s] = t;
            g_slot_weight[s]   = w2v[q];
        }
        return;
    }

    if (bid <= X_BLKS) {
        const size_t base = (size_t)(bid - 1) * 1024;
        conv_block_1024(x + base, ((uint2*)g_xh) + base, tid);
        return;
    }

    const size_t base = (size_t)(bid - 1 - X_BLKS) * 1024;
    conv_block_1024(w13 + base, ((uint2*)g_wh13) + base, tid);
}

// ============================================================
// Fragments via ldmatrix.x4. 16 warps: wm=wid&3 (32 rows), wn=wid>>2 (32 cols).
// Chunk k64 = 4 k16 steps.
// ============================================================
struct FragAddr {
    uint32_t a[2];
    uint32_t b[2];
};

__device__ __forceinline__ FragAddr make_frag_addrs(uint32_t smBase, int wid, int lid) {
    FragAddr fa;
    const int wm = wid & 3, wn = wid >> 2;
#pragma unroll
    for (int mf = 0; mf < 2; mf++) {
        const int row = wm * 32 + mf * 16 + (lid & 15);
        fa.a[mf] = smBase + row * ROW_B + (lid >> 4) * 16;
    }
#pragma unroll
    for (int np = 0; np < 2; np++) {
        const int n = wn * 32 + np * 16 + ((lid >> 4) * 8) + (lid & 7);
        fa.b[np] = smBase + A_HALVES * 2 + n * ROW_B + ((lid >> 3) & 1) * 16;
    }
    return fa;
}

__device__ __forceinline__ void mma_chunk(const FragAddr& fa, uint32_t stOff,
                                          float acc[2][4][4]) {
#pragma unroll
    for (int ks = 0; ks < 4; ks++) {
        const uint32_t kb = stOff + ks * 32;
        uint32_t af[2][4];
#pragma unroll
        for (int mf = 0; mf < 2; mf++)
            LDSM_X4(af[mf][0], af[mf][1], af[mf][2], af[mf][3], fa.a[mf] + kb);
        uint32_t bf[4][2];
#pragma unroll
        for (int np = 0; np < 2; np++)
            LDSM_X4(bf[2 * np][0], bf[2 * np][1], bf[2 * np + 1][0], bf[2 * np + 1][1],
                    fa.b[np] + kb);
#pragma unroll
        for (int mf = 0; mf < 2; mf++)
#pragma unroll
            for (int nf = 0; nf < 4; nf++)
                mma_f16(acc[mf][nf], af[mf], bf[nf]);
    }
}

__device__ __forceinline__ void issue_chunk(uint32_t aDst, uint32_t bDst,
                                            const __half* aSrc, const __half* bSrc,
                                            int kOff, int sb) {
    CP_ASYNC16(aDst,      aSrc + kOff + sb * 8);
    CP_ASYNC16(aDst + 64, aSrc + kOff + sb * 8 + 32);
    CP_ASYNC16(bDst,      bSrc + kOff + sb * 8);
    CP_ASYNC16(bDst + 64, bSrc + kOff + sb * 8 + 32);
    CP_COMMIT();
}

// ============================================================
// GEMM1 + SiLU*up, with conv_w2 fused as filler blocks (blockIdx.y >= NB1Y).
// grid = (MAXTILES, NB1Y + CONV_ROWS)
// ============================================================
__global__ __launch_bounds__(NTHREADS, 2)
void gemm1_mma(const float4* __restrict__ w2src) {
    // ---- conv_w2 filler blocks (disjoint from gemm1 data; consumed by gemm2) ----
    if (blockIdx.y >= NB1Y) {
        const int c = (blockIdx.y - NB1Y) * gridDim.x + blockIdx.x;
        if (c < W2_SLICES) {
            const float4* src = w2src + (size_t)c * W2_PER_BLK;
            uint2* dst = ((uint2*)g_wh2) + (size_t)c * W2_PER_BLK;
#pragma unroll 2
            for (int i = threadIdx.x; i < W2_PER_BLK; i += NTHREADS)
                dst[i] = cvt4(src[i]);
        }
        return;
    }

    const int tile_m = blockIdx.x;
    if (tile_m >= g_num_tiles) return;
    const int e   = g_tile_expert[tile_m];
    const int nbJ = blockIdx.y * 64;

    extern __shared__ __half smh[];

    const int tid = threadIdx.x;
    const int wid = tid >> 5, lid = tid & 31;
    const int fg = lid >> 2, ftg = lid & 3;
    const int fwm = wid & 3, fwn = wid >> 2;

    const int r  = tid >> 2;            // 0..127
    const int sb = tid & 3;             // seg 0..3 (pairs with sb+4)
    const int tokr = g_token_of_slot[tile_m * BM + r];
    const __half* aSrc = g_xh + (size_t)(tokr < 0 ? 0 : tokr) * H_DIM;
    const int j = r >> 1;
    const int wrow = (r & 1) ? (I_DIM + nbJ + j) : (nbJ + j);
    const __half* bSrc = g_wh13 + ((size_t)e * 2 * I_DIM + wrow) * H_DIM;

    const uint32_t smBase = smem_u32(smh);
    const FragAddr fa = make_frag_addrs(smBase, wid, lid);
    uint32_t aDst[NSTAGE], bDst[NSTAGE];
#pragma unroll
    for (int s = 0; s < NSTAGE; s++) {
        aDst[s] = smBase + s * STAGE_BYTES + r * ROW_B + sb * 16;
        bDst[s] = aDst[s] + A_HALVES * 2;
    }

    float acc[2][4][4];
#pragma unroll
    for (int a = 0; a < 2; a++)
#pragma unroll
        for (int b = 0; b < 4; b++)
#pragma unroll
            for (int c = 0; c < 4; c++) acc[a][b][c] = 0.f;

    const int NC = H_DIM / BK;   // 32
    issue_chunk(aDst[0], bDst[0], aSrc, bSrc, 0 * BK, sb);
    issue_chunk(aDst[1], bDst[1], aSrc, bSrc, 1 * BK, sb);

    int stage = 0, stage2 = 2;
#pragma unroll 1
    for (int c = 0; c < NC; c++) {
        if (c + 1 < NC) CP_WAIT(1); else CP_WAIT(0);
        __syncthreads();
        if (c + 2 < NC)
            issue_chunk(aDst[stage2], bDst[stage2], aSrc, bSrc, (c + 2) * BK, sb);
        mma_chunk(fa, (uint32_t)(stage * STAGE_BYTES), acc);
        stage = (stage + 1 == NSTAGE) ? 0 : stage + 1;
        stage2 = (stage2 + 1 == NSTAGE) ? 0 : stage2 + 1;
    }

    // epilogue: silu(gate)*up; c-pair (even,odd) = (gate, up) of same col; store fp16
#pragma unroll
    for (int mf = 0; mf < 2; mf++) {
#pragma unroll
        for (int half = 0; half < 2; half++) {
            const int slot = tile_m * BM + fwm * 32 + mf * 16 + fg + half * 8;
            if (g_token_of_slot[slot] >= 0) {
                __half* dst = g_act + (size_t)slot * I_DIM + nbJ;
#pragma unroll
                for (int nf = 0; nf < 4; nf++) {
                    const int jj = fwn * 16 + nf * 4 + ftg;
                    const float gt = acc[mf][nf][half * 2 + 0];
                    const float up = acc[mf][nf][half * 2 + 1];
                    dst[jj] = __float2half_rn(up * gt / (1.f + expf(-gt)));
                }
            }
        }
    }
}

// ============================================================
// GEMM2 + weighted scatter via red.global.v2.f32. grid = (MAXTILES, H/128)
// ============================================================
__global__ __launch_bounds__(NTHREADS, 2)
void gemm2_mma(float* __restrict__ out) {
    const int tile_m = blockIdx.x;
    if (tile_m >= g_num_tiles) return;
    const int e     = g_tile_expert[tile_m];
    const int nbase = blockIdx.y * BN;

    extern __shared__ __half smh[];

    const int tid = threadIdx.x;
    const int wid = tid >> 5, lid = tid & 31;
    const int fg = lid >> 2, ftg = lid & 3;
    const int fwm = wid & 3, fwn = wid >> 2;

    const int r  = tid >> 2;
    const int sb = tid & 3;
    const __half* aSrc = g_act + (size_t)(tile_m * BM + r) * I_DIM;  // pad rows: garbage, rows discarded
    const __half* bSrc = g_wh2 + ((size_t)e * H_DIM + (nbase + r)) * I_DIM;

    const uint32_t smBase = smem_u32(smh);
    const FragAddr fa = make_frag_addrs(smBase, wid, lid);
    uint32_t aDst[NSTAGE], bDst[NSTAGE];
#pragma unroll
    for (int s = 0; s < NSTAGE; s++) {
        aDst[s] = smBase + s * STAGE_BYTES + r * ROW_B + sb * 16;
        bDst[s] = aDst[s] + A_HALVES * 2;
    }

    float acc[2][4][4];
#pragma unroll
    for (int a = 0; a < 2; a++)
#pragma unroll
        for (int b = 0; b < 4; b++)
#pragma unroll
            for (int c = 0; c < 4; c++) acc[a][b][c] = 0.f;

    const int NC = I_DIM / BK;   // 22
    issue_chunk(aDst[0], bDst[0], aSrc, bSrc, 0 * BK, sb);
    issue_chunk(aDst[1], bDst[1], aSrc, bSrc, 1 * BK, sb);

    int stage = 0, stage2 = 2;
#pragma unroll 1
    for (int c = 0; c < NC; c++) {
        if (c + 1 < NC) CP_WAIT(1); else CP_WAIT(0);
        __syncthreads();
        if (c + 2 < NC)
            issue_chunk(aDst[stage2], bDst[stage2], aSrc, bSrc, (c + 2) * BK, sb);
        mma_chunk(fa, (uint32_t)(stage * STAGE_BYTES), acc);
        stage = (stage + 1 == NSTAGE) ? 0 : stage + 1;
        stage2 = (stage2 + 1 == NSTAGE) ? 0 : stage2 + 1;
    }

#pragma unroll
    for (int mf = 0; mf < 2; mf++) {
#pragma unroll
        for (int half = 0; half < 2; half++) {
            const int slot = tile_m * BM + fwm * 32 + mf * 16 + fg + half * 8;
            const int tok  = g_token_of_slot[slot];
            if (tok >= 0) {
                const float w = g_slot_weight[slot];
                float* dst = out + (size_t)tok * H_DIM + nbase;
#pragma unroll
                for (int nf = 0; nf < 4; nf++) {
                    const int col = fwn * 32 + nf * 8 + ftg * 2;   // even -> 8B aligned
                    REDG_ADD_V2(dst + col,
                                w * acc[mf][nf][half * 2 + 0],
                                w * acc[mf][nf][half * 2 + 1]);
                }
            }
        }
    }
}

// ============================================================
extern "C" void kernel_launch(void* const* d_in, const int* in_sizes, int n_in,
                              void* d_out, int out_size) {
    const float* x      = (const float*)d_in[0];   // [1024, 2048]
    const float* logits = (const float*)d_in[1];   // [1024, 8]
    const float* w13    = (const float*)d_in[2];   // [8, 2816, 2048]
    const float* w2     = (const float*)d_in[3];   // [8, 2048, 1408]
    float* out = (float*)d_out;                    // [1024, 2048]
    (void)in_sizes; (void)n_in;

    cudaFuncSetAttribute(gemm1_mma, cudaFuncAttributeMaxDynamicSharedMemorySize, SMEM_DYN_BYTES);
    cudaFuncSetAttribute(gemm2_mma, cudaFuncAttributeMaxDynamicSharedMemorySize, SMEM_DYN_BYTES);

    cudaMemsetAsync(d_out, 0, (size_t)out_size * sizeof(float));
    prep_kernel<<<PREP_BLKS, 256>>>(logits, (const float4*)x, (const float4*)w13);
    // gemm1 grid carries 512 conv_w2 filler blocks (blockIdx.y >= NB1Y)
    gemm1_mma<<<dim3(MAXTILES, NB1Y + CONV_ROWS), NTHREADS, SMEM_DYN_BYTES>>>((const float4*)w2);
    gemm2_mma<<<dim3(MAXTILES, H_DIM / BN), NTHREADS, SMEM_DYN_BYTES>>>(out);
}